// round 1
// baseline (speedup 1.0000x reference)
#include <cuda_runtime.h>
#include <math.h>

#define IH 256
#define IW 704
#define FH 32
#define FW 88
#define PIX (FH*FW)          // 2816
#define BATCH 2
#define C_IN 256
#define HID 64
#define DEPTH 118
#define C_OUT 80
#define OUT2 (DEPTH + C_OUT) // 198
#define NR 128
#define NT 256
#define PI_D 3.141592653589793

// ---------------- device scratch (no allocation allowed) ----------------
__device__ float g_w1f[C_IN*HID];     // [c][o]
__device__ float g_c1[HID];
__device__ float g_w2f[OUT2*HID];     // [o][c]
__device__ float g_c2[OUT2];
__device__ float g_h[BATCH*HID*PIX];
__device__ float g_depth[BATCH*PIX*DEPTH];
__device__ float g_feat[BATCH*PIX*C_OUT];
__device__ float g_bev[BATCH*NR*NT*C_OUT];   // [bin][80] channel-contiguous
__device__ float g_radE[NR+1];
__device__ float g_angE[NT+1];

// ---------------- K0: fold BN into weights, build edge tables ----------------
__global__ void k0_prep(const float* __restrict__ w1, const float* __restrict__ b1,
                        const float* __restrict__ g1, const float* __restrict__ be1,
                        const float* __restrict__ m1, const float* __restrict__ v1,
                        const float* __restrict__ w2, const float* __restrict__ b2,
                        const float* __restrict__ g2, const float* __restrict__ be2,
                        const float* __restrict__ m2, const float* __restrict__ v2)
{
    int t = threadIdx.x;
    int nth = blockDim.x;
    // radial edges: numpy t = linspace(0,1,129) (exact i/128), rad = 1 + t^1.5*59 in f64, cast f32
    for (int i = t; i <= NR; i += nth) {
        double tt = (i == NR) ? 1.0 : (double)i * (1.0/128.0);
        g_radE[i] = (float)(1.0 + pow(tt, 1.5) * 59.0);
    }
    // angular edges: linspace(-pi/2, pi/2, 257) in f64, endpoint exact
    for (int i = t; i <= NT; i += nth) {
        double a = (i == NT) ? (PI_D * 0.5) : (-PI_D * 0.5 + (double)i * (PI_D / 256.0));
        g_angE[i] = (float)a;
    }
    for (int i = t; i < C_IN*HID; i += nth) {
        int o = i & (HID-1); int c = i >> 6;
        float inv = g1[o] / sqrtf(v1[o] + 1e-5f);
        g_w1f[i] = w1[o*C_IN + c] * inv;
    }
    for (int o = t; o < HID; o += nth) {
        float inv = g1[o] / sqrtf(v1[o] + 1e-5f);
        g_c1[o] = b1[o]*inv + be1[o] - m1[o]*inv;
    }
    for (int i = t; i < OUT2*HID; i += nth) {
        int o = i >> 6;
        float inv = g2[o] / sqrtf(v2[o] + 1e-5f);
        g_w2f[i] = w2[i] * inv;
    }
    for (int o = t; o < OUT2; o += nth) {
        float inv = g2[o] / sqrtf(v2[o] + 1e-5f);
        g_c2[o] = b2[o]*inv + be2[o] - m2[o]*inv;
    }
}

// ---------------- K1: GEMM1 (256 -> 64) + ReLU, tiled 64 pixels per block ----------------
__global__ void __launch_bounds__(256) k1_gemm1(const float* __restrict__ x)
{
    __shared__ float xs[64*64];
    __shared__ float ws[64*64];
    int blk = blockIdx.x;               // 88 blocks (44 tiles per image)
    int b = blk / 44;
    int pixbase = (blk % 44) * 64;
    int t = threadIdx.x;
    int o = t & 63;
    int pg = t >> 6;                    // 0..3, 16 pixels each

    float acc[16];
#pragma unroll
    for (int j = 0; j < 16; j++) acc[j] = 0.f;

    for (int cc = 0; cc < 4; cc++) {
        __syncthreads();
#pragma unroll
        for (int i = 0; i < 16; i++) {
            int idx = t + i*256;
            int cl = idx >> 6, p = idx & 63;
            xs[idx] = x[(b*C_IN + cc*64 + cl)*PIX + pixbase + p];
            ws[idx] = g_w1f[cc*4096 + idx];
        }
        __syncthreads();
#pragma unroll 8
        for (int cl = 0; cl < 64; cl++) {
            float w = ws[cl*64 + o];
            const float4* xr = (const float4*)&xs[cl*64 + pg*16];
            float4 a0 = xr[0], a1 = xr[1], a2 = xr[2], a3 = xr[3];
            acc[0]  += w*a0.x; acc[1]  += w*a0.y; acc[2]  += w*a0.z; acc[3]  += w*a0.w;
            acc[4]  += w*a1.x; acc[5]  += w*a1.y; acc[6]  += w*a1.z; acc[7]  += w*a1.w;
            acc[8]  += w*a2.x; acc[9]  += w*a2.y; acc[10] += w*a2.z; acc[11] += w*a2.w;
            acc[12] += w*a3.x; acc[13] += w*a3.y; acc[14] += w*a3.z; acc[15] += w*a3.w;
        }
    }
    float bias = g_c1[o];
    int base = (b*HID + o)*PIX + pixbase + pg*16;
#pragma unroll
    for (int j = 0; j < 16; j++) {
        float v = acc[j] + bias;
        g_h[base + j] = v > 0.f ? v : 0.f;
    }
}

// ---------------- K2: GEMM2 (64 -> 198) + BN + softmax, one block per pixel ----------------
__global__ void __launch_bounds__(256) k2_gemm2()
{
    int blk = blockIdx.x;
    int b = blk / PIX, pix = blk % PIX;
    int t = threadIdx.x;

    __shared__ float hsh[HID];
    __shared__ float vals[256];
    __shared__ float red[128];

    if (t < HID) hsh[t] = g_h[(b*HID + t)*PIX + pix];
    __syncthreads();

    if (t < OUT2) {
        float acc = 0.f;
        const float4* wr = (const float4*)&g_w2f[t*HID];
#pragma unroll
        for (int c4 = 0; c4 < 16; c4++) {
            float4 w = wr[c4];
            acc += w.x*hsh[c4*4] + w.y*hsh[c4*4+1] + w.z*hsh[c4*4+2] + w.w*hsh[c4*4+3];
        }
        vals[t] = acc + g_c2[t];
    }
    __syncthreads();

    if (t < 128) red[t] = (t < DEPTH) ? vals[t] : -INFINITY;
    __syncthreads();
    for (int s = 64; s > 0; s >>= 1) {
        if (t < s) red[t] = fmaxf(red[t], red[t+s]);
        __syncthreads();
    }
    float mx = red[0];
    __syncthreads();
    float e = 0.f;
    if (t < DEPTH) e = expf(vals[t] - mx);
    if (t < 128) red[t] = (t < DEPTH) ? e : 0.f;
    __syncthreads();
    for (int s = 64; s > 0; s >>= 1) {
        if (t < s) red[t] += red[t+s];
        __syncthreads();
    }
    float sum = red[0];
    if (t < DEPTH)       g_depth[(b*PIX + pix)*DEPTH + t] = e / sum;
    else if (t < OUT2)   g_feat[(b*PIX + pix)*C_OUT + (t - DEPTH)] = vals[t];
}

// ---------------- K zero: clear BEV scratch ----------------
__global__ void k_zero()
{
    int n = BATCH*NR*NT*C_OUT/4;
    float4 z = make_float4(0.f, 0.f, 0.f, 0.f);
    for (int i = blockIdx.x*blockDim.x + threadIdx.x; i < n; i += gridDim.x*blockDim.x)
        ((float4*)g_bev)[i] = z;
}

// ---------------- K3: lift + polar bin + run-compressed vector-atomic scatter ----------------
__device__ __forceinline__ int upper_bound_sh(const float* a, int n, float v)
{
    int lo = 0, hi = n;
    while (lo < hi) {
        int m = (lo + hi) >> 1;
        if (a[m] <= v) lo = m + 1; else hi = m;
    }
    return lo;
}

__global__ void __launch_bounds__(128) k3_scatter(const float* __restrict__ rots,
                                                  const float* __restrict__ trans,
                                                  const float* __restrict__ intr)
{
    int blk = blockIdx.x;
    int b = blk / PIX, pix = blk % PIX;
    int t = threadIdx.x;

    __shared__ float dsh[DEPTH];
    __shared__ float4 fsh[20];
    __shared__ int   binsh[DEPTH];
    __shared__ int   headBin[DEPTH];
    __shared__ float headW[DEPTH];
    __shared__ int   nheads;
    __shared__ float radE[NR+1];
    __shared__ float angE[NT+1];

    if (t == 0) nheads = 0;
    for (int i = t; i < NR+1; i += 128) radE[i] = g_radE[i];
    for (int i = t; i < NT+1; i += 128) angE[i] = g_angE[i];
    if (t < DEPTH) dsh[t] = g_depth[(b*PIX + pix)*DEPTH + t];
    if (t < 20)    fsh[t] = ((const float4*)g_feat)[(b*PIX + pix)*20 + t];
    __syncthreads();

    if (t < DEPTH) {
        int wi = pix % FW, hi = pix / FW;
        float u = (wi == FW-1) ? (float)(IW-1) : (float)((double)wi * ((double)(IW-1)/(FW-1)));
        float v = (hi == FH-1) ? (float)(IH-1) : (float)((double)hi * ((double)(IH-1)/(FH-1)));
        float fx = intr[b*9 + 0], fy = intr[b*9 + 4];
        float cx = intr[b*9 + 2], cy = intr[b*9 + 5];
        float dv = 1.0f + 0.5f * (float)t;
        float pcx = (u - cx) * dv / fx;
        float pcy = (v - cy) * dv / fy;
        float pcz = dv;
        const float* R = &rots[b*9];
        const float* tr = &trans[b*3];
        float xl = R[0]*pcx + R[1]*pcy + R[2]*pcz + tr[0];
        float yl = R[3]*pcx + R[4]*pcy + R[5]*pcz + tr[1];
        float r  = sqrtf(xl*xl + yl*yl);
        float th = atan2f(yl, xl);
        int ri = upper_bound_sh(radE, NR+1, r)  - 1;
        int ti = upper_bound_sh(angE, NT+1, th) - 1;
        int bin = -1;
        if (ri >= 0 && ri < NR && ti >= 0 && ti < NT)
            bin = (b*NR + ri)*NT + ti;
        binsh[t] = bin;
    }
    __syncthreads();

    // run-length compress equal consecutive bins along depth
    if (t < DEPTH) {
        int bn = binsh[t];
        if (bn >= 0 && (t == 0 || binsh[t-1] != bn)) {
            float w = dsh[t];
            int k = t + 1;
            while (k < DEPTH && binsh[k] == bn) { w += dsh[k]; k++; }
            int s = atomicAdd(&nheads, 1);
            headBin[s] = bn;
            headW[s]  = w;
        }
    }
    __syncthreads();

    int tot = nheads * 20;
    for (int i = t; i < tot; i += 128) {
        int h = i / 20;
        int q = i - h*20;
        float w = headW[h];
        float4 f = fsh[q];
        float4* p = (float4*)&g_bev[headBin[h]*C_OUT] + q;
        asm volatile("red.global.add.v4.f32 [%0], {%1,%2,%3,%4};"
                     :: "l"(p), "f"(w*f.x), "f"(w*f.y), "f"(w*f.z), "f"(w*f.w)
                     : "memory");
    }
}

// ---------------- K4: transpose [b][rt][c] -> out [b][c][rt] ----------------
__global__ void k4_transpose(float* __restrict__ out)
{
    __shared__ float tile[32][33];
    int b   = blockIdx.z;
    int rt0 = blockIdx.x * 32;
    int c0  = blockIdx.y * 32;
    int tx = threadIdx.x, ty = threadIdx.y;   // 32 x 8
#pragma unroll
    for (int i = 0; i < 32; i += 8) {
        int rt = rt0 + ty + i, c = c0 + tx;
        tile[ty+i][tx] = (c < C_OUT) ? g_bev[(b*(NR*NT) + rt)*C_OUT + c] : 0.f;
    }
    __syncthreads();
#pragma unroll
    for (int i = 0; i < 32; i += 8) {
        int c = c0 + ty + i, rt = rt0 + tx;
        if (c < C_OUT)
            out[(b*C_OUT + c)*(NR*NT) + rt] = tile[tx][ty+i];
    }
}

// ---------------- launch ----------------
extern "C" void kernel_launch(void* const* d_in, const int* in_sizes, int n_in,
                              void* d_out, int out_size)
{
    const float* x     = (const float*)d_in[0];
    const float* rots  = (const float*)d_in[1];
    const float* trans = (const float*)d_in[2];
    const float* intr  = (const float*)d_in[3];
    const float* w1    = (const float*)d_in[4];
    const float* b1    = (const float*)d_in[5];
    const float* g1    = (const float*)d_in[6];
    const float* be1   = (const float*)d_in[7];
    const float* m1    = (const float*)d_in[8];
    const float* v1    = (const float*)d_in[9];
    const float* w2    = (const float*)d_in[10];
    const float* b2    = (const float*)d_in[11];
    const float* g2    = (const float*)d_in[12];
    const float* be2   = (const float*)d_in[13];
    const float* m2    = (const float*)d_in[14];
    const float* v2    = (const float*)d_in[15];
    float* out = (float*)d_out;

    k0_prep<<<1, 512>>>(w1, b1, g1, be1, m1, v1, w2, b2, g2, be2, m2, v2);
    k1_gemm1<<<88, 256>>>(x);
    k2_gemm2<<<BATCH*PIX, 256>>>();
    k_zero<<<2048, 256>>>();
    k3_scatter<<<BATCH*PIX, 128>>>(rots, trans, intr);
    k4_transpose<<<dim3((NR*NT)/32, (C_OUT+31)/32, BATCH), dim3(32, 8)>>>(out);
}

// round 2
// speedup vs baseline: 1.3182x; 1.3182x over previous
#include <cuda_runtime.h>
#include <math.h>

#define IH 256
#define IW 704
#define FH 32
#define FW 88
#define PIX (FH*FW)          // 2816
#define BATCH 2
#define C_IN 256
#define HID 64
#define DEPTH 118
#define C_OUT 80
#define OUT2 (DEPTH + C_OUT) // 198
#define NR 128
#define NT 256
#define PI_D 3.141592653589793

// ---------------- device scratch ----------------
__device__ float g_w1f[C_IN*HID];     // [c][o]
__device__ float g_c1[HID];
__device__ float g_w2f[OUT2*HID];     // [o][c]
__device__ float g_c2[OUT2];
__device__ float g_h[BATCH*PIX*HID];  // [b][pix][hid]
__device__ __align__(16) float g_bev[BATCH*NR*NT*C_OUT];  // [bin][80]
__device__ float g_radE[NR+1];
__device__ float g_angE[NT+1];

// ---------------- K0: zero bev + fold BN into weights + edge tables ----------------
__global__ void kprep(const float* __restrict__ w1, const float* __restrict__ b1,
                      const float* __restrict__ g1, const float* __restrict__ be1,
                      const float* __restrict__ m1, const float* __restrict__ v1,
                      const float* __restrict__ w2, const float* __restrict__ b2,
                      const float* __restrict__ g2, const float* __restrict__ be2,
                      const float* __restrict__ m2, const float* __restrict__ v2)
{
    int gt = blockIdx.x*blockDim.x + threadIdx.x;
    float4 z = make_float4(0.f,0.f,0.f,0.f);
    int n4 = BATCH*NR*NT*C_OUT/4;
    for (int i = gt; i < n4; i += gridDim.x*blockDim.x)
        ((float4*)g_bev)[i] = z;

    if (blockIdx.x == 0) {
        int t = threadIdx.x, nth = blockDim.x;
        for (int i = t; i <= NR; i += nth) {
            double tt = (i == NR) ? 1.0 : (double)i * (1.0/128.0);
            g_radE[i] = (float)(1.0 + pow(tt, 1.5) * 59.0);
        }
        for (int i = t; i <= NT; i += nth) {
            double a = (i == NT) ? (PI_D*0.5) : (-PI_D*0.5 + (double)i * (PI_D/256.0));
            g_angE[i] = (float)a;
        }
        for (int i = t; i < C_IN*HID; i += nth) {
            int o = i & (HID-1); int c = i >> 6;
            float inv = g1[o] / sqrtf(v1[o] + 1e-5f);
            g_w1f[i] = w1[o*C_IN + c] * inv;
        }
        for (int o = t; o < HID; o += nth) {
            float inv = g1[o] / sqrtf(v1[o] + 1e-5f);
            g_c1[o] = b1[o]*inv + be1[o] - m1[o]*inv;
        }
        for (int i = t; i < OUT2*HID; i += nth) {
            int o = i >> 6;
            float inv = g2[o] / sqrtf(v2[o] + 1e-5f);
            g_w2f[i] = w2[i] * inv;
        }
        for (int o = t; o < OUT2; o += nth) {
            float inv = g2[o] / sqrtf(v2[o] + 1e-5f);
            g_c2[o] = b2[o]*inv + be2[o] - m2[o]*inv;
        }
    }
}

// ---------------- K1: GEMM1 (256 -> 64) + ReLU; 32 pixels/block, out [pix][hid] ----------------
__global__ void __launch_bounds__(256) k1_gemm1(const float* __restrict__ x)
{
    __shared__ float xs[64*32];   // [c][pix]
    __shared__ float ws[64*64];   // [c][o]
    int blk = blockIdx.x;                 // 176 = 2 * 88
    int b = blk / 88;
    int pixbase = (blk % 88) * 32;
    int t = threadIdx.x;
    int o  = t & 63;
    int pg = t >> 6;                      // 0..3 -> 8 pixels each

    float acc[8];
#pragma unroll
    for (int j = 0; j < 8; j++) acc[j] = 0.f;

    for (int cc = 0; cc < 4; cc++) {
        __syncthreads();
#pragma unroll
        for (int i = 0; i < 8; i++) {
            int idx = t + i*256;          // 2048 = 64ch * 32pix
            int cl = idx >> 5, p = idx & 31;
            xs[idx] = x[(b*C_IN + cc*64 + cl)*PIX + pixbase + p];
        }
#pragma unroll
        for (int i = 0; i < 16; i++) {
            int idx = t + i*256;          // 4096
            ws[idx] = g_w1f[cc*4096 + idx];
        }
        __syncthreads();
#pragma unroll 8
        for (int cl = 0; cl < 64; cl++) {
            float w = ws[cl*64 + o];
            const float4* xr = (const float4*)&xs[cl*32 + pg*8];
            float4 a0 = xr[0], a1 = xr[1];
            acc[0] += w*a0.x; acc[1] += w*a0.y; acc[2] += w*a0.z; acc[3] += w*a0.w;
            acc[4] += w*a1.x; acc[5] += w*a1.y; acc[6] += w*a1.z; acc[7] += w*a1.w;
        }
    }
    float bias = g_c1[o];
#pragma unroll
    for (int j = 0; j < 8; j++) {
        float v = acc[j] + bias;
        g_h[(b*PIX + pixbase + pg*8 + j)*HID + o] = v > 0.f ? v : 0.f;
    }
}

// ---------------- geometry helper ----------------
__device__ __forceinline__ int upper_bound_sh(const float* a, int n, float v)
{
    int lo = 0, hi = n;
    while (lo < hi) {
        int m = (lo + hi) >> 1;
        if (a[m] <= v) lo = m + 1; else hi = m;
    }
    return lo;
}

__device__ __forceinline__ int computeBin(int wi, int row, int d,
                                          const float* cam, const float* in4,
                                          const float* radE, const float* angE)
{
    float u = (wi == FW-1) ? (float)(IW-1) : (float)((double)wi * ((double)(IW-1)/(FW-1)));
    float v = (row == FH-1) ? (float)(IH-1) : (float)((double)row * ((double)(IH-1)/(FH-1)));
    float dv = 1.0f + 0.5f * (float)d;
    float pcx = (u - in4[2]) * dv / in4[0];
    float pcy = (v - in4[3]) * dv / in4[1];
    float pcz = dv;
    float xl = cam[0]*pcx + cam[1]*pcy + cam[2]*pcz + cam[9];
    float yl = cam[3]*pcx + cam[4]*pcy + cam[5]*pcz + cam[10];
    float r  = sqrtf(xl*xl + yl*yl);
    float th = atan2f(yl, xl);
    int ri = upper_bound_sh(radE, NR+1, r)  - 1;
    int ti = upper_bound_sh(angE, NT+1, th) - 1;
    if (ri < 0 || ri >= NR || ti < 0 || ti >= NT) return -1;
    return ri*NT + ti;
}

// ---------------- K23: GEMM2 + BN + softmax + lift + scatter (block = one column) ----------------
__global__ void __launch_bounds__(256) k23_fused(const float* __restrict__ rots,
                                                 const float* __restrict__ trans,
                                                 const float* __restrict__ intr)
{
    __shared__ float vsh[32*201];     // [row][198] padded to 201 (depth then feat)
    __shared__ float uni[118*32];     // phase1: hsh[c*33+row] (2112) ; phase2: wsum[h*32+row]
    __shared__ float radE[NR+1], angE[NT+1];
    __shared__ int   bins0[DEPTH];
    __shared__ int   headBin[DEPTH], headS[DEPTH], headE[DEPTH];
    __shared__ int   nheads, eqflag;
    __shared__ float cam[12];
    __shared__ float in4[4];

    int blk = blockIdx.x;             // 176 = 2 batches * 88 columns
    int b = blk / FW, wi = blk % FW;
    int t = threadIdx.x;

    for (int i = t; i < NR+1; i += 256) radE[i] = g_radE[i];
    for (int i = t; i < NT+1; i += 256) angE[i] = g_angE[i];
    if (t < 9) cam[t] = rots[b*9 + t];
    if (t < 3) cam[9+t] = trans[b*3 + t];
    if (t == 0) {
        in4[0] = intr[b*9 + 0]; in4[1] = intr[b*9 + 4];
        in4[2] = intr[b*9 + 2]; in4[3] = intr[b*9 + 5];
        nheads = 0; eqflag = 1;
    }

    // load hidden for 32 rows of this column: hsh[c*33 + row]
    float* hsh = uni;
    for (int i = t; i < 2048; i += 256) {
        int row = i >> 6, c = i & 63;
        hsh[c*33 + row] = g_h[(b*PIX + row*FW + wi)*HID + c];
    }
    __syncthreads();

    // GEMM2: 32 pixels x 198 outputs, dot over 64
    int pix = t & 31, og = t >> 5;
#pragma unroll 5
    for (int k = 0; k < 25; k++) {
        int o = og + 8*k;
        if (o < OUT2) {
            const float4* wr = (const float4*)&g_w2f[o*HID];
            float acc = 0.f;
#pragma unroll
            for (int c4 = 0; c4 < 16; c4++) {
                float4 w = wr[c4];
                acc += w.x*hsh[(4*c4+0)*33 + pix] + w.y*hsh[(4*c4+1)*33 + pix]
                     + w.z*hsh[(4*c4+2)*33 + pix] + w.w*hsh[(4*c4+3)*33 + pix];
            }
            vsh[pix*201 + o] = acc + g_c2[o];
        }
    }
    __syncthreads();

    // softmax over first 118 channels, per pixel (warp handles 4 pixels)
    int lane = t & 31, warp = t >> 5;
    for (int j = 0; j < 4; j++) {
        int p = warp*4 + j;
        float a0 = vsh[p*201 + lane];
        float a1 = vsh[p*201 + lane + 32];
        float a2 = vsh[p*201 + lane + 64];
        float a3 = (lane + 96 < DEPTH) ? vsh[p*201 + lane + 96] : -INFINITY;
        float m = fmaxf(fmaxf(a0,a1), fmaxf(a2,a3));
#pragma unroll
        for (int s = 16; s; s >>= 1) m = fmaxf(m, __shfl_xor_sync(~0u, m, s));
        float e0 = expf(a0 - m), e1 = expf(a1 - m), e2 = expf(a2 - m);
        float e3 = (lane + 96 < DEPTH) ? expf(a3 - m) : 0.f;
        float sm = e0 + e1 + e2 + e3;
#pragma unroll
        for (int s = 16; s; s >>= 1) sm += __shfl_xor_sync(~0u, sm, s);
        float inv = 1.f / sm;
        vsh[p*201 + lane]      = e0*inv;
        vsh[p*201 + lane + 32] = e1*inv;
        vsh[p*201 + lane + 64] = e2*inv;
        if (lane + 96 < DEPTH) vsh[p*201 + lane + 96] = e3*inv;
    }
    __syncthreads();

    // bins for row 0; check all rows identical (true for this camera geometry)
    if (t < DEPTH) bins0[t] = computeBin(wi, 0, t, cam, in4, radE, angE);
    __syncthreads();
    for (int i = t; i < 31*DEPTH; i += 256) {
        int row = 1 + i/DEPTH, d = i % DEPTH;
        if (computeBin(wi, row, d, cam, in4, radE, angE) != bins0[d]) eqflag = 0;
    }
    __syncthreads();

    if (eqflag) {
        // run-compress row0 bins
        if (t < DEPTH) {
            int bn = bins0[t];
            if (bn >= 0 && (t == 0 || bins0[t-1] != bn)) {
                int k = t + 1;
                while (k < DEPTH && bins0[k] == bn) k++;
                int s = atomicAdd(&nheads, 1);
                headBin[s] = bn + b*NR*NT; headS[s] = t; headE[s] = k;
            }
        }
        __syncthreads();
        int nh = nheads;
        // per-head, per-row depth weight
        float* wsum = uni;   // hsh is dead
        for (int i = t; i < nh*32; i += 256) {
            int h = i >> 5, row = i & 31;
            float s = 0.f;
            for (int d = headS[h]; d < headE[h]; d++) s += vsh[row*201 + d];
            wsum[h*32 + row] = s;
        }
        __syncthreads();
        // aggregate 32 rows -> one v4 RED per (head, channel-quad)
        for (int i = t; i < nh*20; i += 256) {
            int h = i/20, q = i - h*20;
            float ax=0.f, ay=0.f, az=0.f, aw=0.f;
#pragma unroll 4
            for (int row = 0; row < 32; row++) {
                float w = wsum[h*32 + row];
                const float* f = &vsh[row*201 + DEPTH + q*4];
                ax += w*f[0]; ay += w*f[1]; az += w*f[2]; aw += w*f[3];
            }
            float4* pdst = (float4*)&g_bev[headBin[h]*C_OUT + q*4];
            asm volatile("red.global.add.v4.f32 [%0], {%1,%2,%3,%4};"
                         :: "l"(pdst), "f"(ax), "f"(ay), "f"(az), "f"(aw) : "memory");
        }
    } else {
        // generic fallback: per-row scatter
        for (int row = 0; row < 32; row++) {
            __syncthreads();
            if (t == 0) nheads = 0;
            __syncthreads();
            if (t < DEPTH) bins0[t] = computeBin(wi, row, t, cam, in4, radE, angE);
            __syncthreads();
            if (t < DEPTH) {
                int bn = bins0[t];
                if (bn >= 0 && (t == 0 || bins0[t-1] != bn)) {
                    int k = t + 1;
                    while (k < DEPTH && bins0[k] == bn) k++;
                    float s = 0.f;
                    for (int d = t; d < k; d++) s += vsh[row*201 + d];
                    int sN = atomicAdd(&nheads, 1);
                    headBin[sN] = bn + b*NR*NT;
                    headS[sN] = __float_as_int(s);
                }
            }
            __syncthreads();
            int nh = nheads;
            for (int i = t; i < nh*20; i += 256) {
                int h = i/20, q = i - h*20;
                float w = __int_as_float(headS[h]);
                const float* f = &vsh[row*201 + DEPTH + q*4];
                float4* pdst = (float4*)&g_bev[headBin[h]*C_OUT + q*4];
                asm volatile("red.global.add.v4.f32 [%0], {%1,%2,%3,%4};"
                             :: "l"(pdst), "f"(w*f[0]), "f"(w*f[1]), "f"(w*f[2]), "f"(w*f[3]) : "memory");
            }
        }
    }
}

// ---------------- K4: transpose [b][rt][c] -> out [b][c][rt] ----------------
__global__ void k4_transpose(float* __restrict__ out)
{
    __shared__ float tile[32][33];
    int b   = blockIdx.z;
    int rt0 = blockIdx.x * 32;
    int c0  = blockIdx.y * 32;
    int tx = threadIdx.x, ty = threadIdx.y;   // 32 x 8
#pragma unroll
    for (int i = 0; i < 32; i += 8) {
        int rt = rt0 + ty + i, c = c0 + tx;
        tile[ty+i][tx] = (c < C_OUT) ? g_bev[(b*(NR*NT) + rt)*C_OUT + c] : 0.f;
    }
    __syncthreads();
#pragma unroll
    for (int i = 0; i < 32; i += 8) {
        int c = c0 + ty + i, rt = rt0 + tx;
        if (c < C_OUT)
            out[(b*C_OUT + c)*(NR*NT) + rt] = tile[tx][ty+i];
    }
}

// ---------------- launch ----------------
extern "C" void kernel_launch(void* const* d_in, const int* in_sizes, int n_in,
                              void* d_out, int out_size)
{
    const float* x     = (const float*)d_in[0];
    const float* rots  = (const float*)d_in[1];
    const float* trans = (const float*)d_in[2];
    const float* intr  = (const float*)d_in[3];
    const float* w1    = (const float*)d_in[4];
    const float* b1    = (const float*)d_in[5];
    const float* g1    = (const float*)d_in[6];
    const float* be1   = (const float*)d_in[7];
    const float* m1    = (const float*)d_in[8];
    const float* v1    = (const float*)d_in[9];
    const float* w2    = (const float*)d_in[10];
    const float* b2    = (const float*)d_in[11];
    const float* g2    = (const float*)d_in[12];
    const float* be2   = (const float*)d_in[13];
    const float* m2    = (const float*)d_in[14];
    const float* v2    = (const float*)d_in[15];
    float* out = (float*)d_out;

    kprep<<<1024, 256>>>(w1, b1, g1, be1, m1, v1, w2, b2, g2, be2, m2, v2);
    k1_gemm1<<<176, 256>>>(x);
    k23_fused<<<176, 256>>>(rots, trans, intr);
    k4_transpose<<<dim3((NR*NT)/32, (C_OUT+31)/32, BATCH), dim3(32, 8)>>>(out);
}

// round 3
// speedup vs baseline: 2.2857x; 1.7339x over previous
#include <cuda_runtime.h>
#include <math.h>

#define IH 256
#define IW 704
#define FH 32
#define FW 88
#define PIX (FH*FW)          // 2816
#define BATCH 2
#define C_IN 256
#define HID 64
#define DEPTH 118
#define C_OUT 80
#define OUT2 (DEPTH + C_OUT) // 198
#define NR 128
#define NT 256
#define PI_D 3.141592653589793
#define VST 204              // vsh row stride (float4 aligned; feat at +120)
#define FOFF 120

// ---------------- device scratch ----------------
__device__ float g_w1f[C_IN*HID];     // [c][o]
__device__ float g_c1[HID];
__device__ float g_w2f[OUT2*HID];     // [o][c]
__device__ float g_c2[OUT2];
__device__ float g_h[BATCH*PIX*HID];  // [b][pix][hid]
__device__ __align__(16) float g_bev[BATCH*NR*NT*C_OUT];  // [bin][80]
__device__ float g_radE[NR+1];
__device__ float g_angE[NT+1];

// ---------------- K0: zero bev + fold BN into weights + edge tables ----------------
__global__ void kprep(const float* __restrict__ w1, const float* __restrict__ b1,
                      const float* __restrict__ g1, const float* __restrict__ be1,
                      const float* __restrict__ m1, const float* __restrict__ v1,
                      const float* __restrict__ w2, const float* __restrict__ b2,
                      const float* __restrict__ g2, const float* __restrict__ be2,
                      const float* __restrict__ m2, const float* __restrict__ v2)
{
    int blk = blockIdx.x, t = threadIdx.x;
    int gt = blk*blockDim.x + t;
    float4 z = make_float4(0.f,0.f,0.f,0.f);
    int n4 = BATCH*NR*NT*C_OUT/4;
    for (int i = gt; i < n4; i += gridDim.x*blockDim.x)
        ((float4*)g_bev)[i] = z;

    if (blk == 0) {
        for (int i = t; i <= NR; i += 256) {
            double tt = (i == NR) ? 1.0 : (double)i * (1.0/128.0);
            g_radE[i] = (float)(1.0 + pow(tt, 1.5) * 59.0);
        }
        for (int i = t; i <= NT; i += 256) {
            double a = (i == NT) ? (PI_D*0.5) : (-PI_D*0.5 + (double)i * (PI_D/256.0));
            g_angE[i] = (float)a;
        }
        for (int o = t; o < HID; o += 256) {
            float inv = g1[o] / sqrtf(v1[o] + 1e-5f);
            g_c1[o] = b1[o]*inv + be1[o] - m1[o]*inv;
        }
        for (int o = t; o < OUT2; o += 256) {
            float inv = g2[o] / sqrtf(v2[o] + 1e-5f);
            g_c2[o] = b2[o]*inv + be2[o] - m2[o]*inv;
        }
    } else if (blk <= 4) {
        __shared__ float inv1[HID];
        if (t < HID) inv1[t] = g1[t] / sqrtf(v1[t] + 1e-5f);
        __syncthreads();
        int base = (blk-1)*4096;
        for (int i = base + t; i < base + 4096; i += 256) {
            int o = i & (HID-1); int c = i >> 6;
            g_w1f[i] = w1[o*C_IN + c] * inv1[o];
        }
    } else if (blk <= 8) {
        __shared__ float inv2[OUT2];
        for (int i = t; i < OUT2; i += 256) inv2[i] = g2[i] / sqrtf(v2[i] + 1e-5f);
        __syncthreads();
        int base = (blk-5)*3168;
        for (int i = base + t; i < base + 3168; i += 256) {
            int o = i >> 6;
            g_w2f[i] = w2[i] * inv2[o];
        }
    }
}

// ---------------- K1: GEMM1 (256 -> 64) + ReLU; 32 pixels/block, out [pix][hid] ----------------
__global__ void __launch_bounds__(256) k1_gemm1(const float* __restrict__ x)
{
    __shared__ float xs[64*32];   // [c][pix]
    __shared__ float ws[64*64];   // [c][o]
    int blk = blockIdx.x;                 // 176 = 2 * 88
    int b = blk / 88;
    int pixbase = (blk % 88) * 32;
    int t = threadIdx.x;
    int o  = t & 63;
    int pg = t >> 6;                      // 0..3 -> 8 pixels each

    float acc[8];
#pragma unroll
    for (int j = 0; j < 8; j++) acc[j] = 0.f;

    for (int cc = 0; cc < 4; cc++) {
        __syncthreads();
#pragma unroll
        for (int i = 0; i < 2; i++) {     // 512 float4 = 64ch * 8 float4
            int j = t + i*256;
            int cl = j >> 3, p4 = j & 7;
            ((float4*)xs)[j] = ((const float4*)(x + (b*C_IN + cc*64 + cl)*PIX + pixbase))[p4];
        }
#pragma unroll
        for (int i = 0; i < 4; i++) {     // 1024 float4
            int j = t + i*256;
            ((float4*)ws)[j] = ((const float4*)g_w1f)[cc*1024 + j];
        }
        __syncthreads();
#pragma unroll 8
        for (int cl = 0; cl < 64; cl++) {
            float w = ws[cl*64 + o];
            const float4* xr = (const float4*)&xs[cl*32 + pg*8];
            float4 a0 = xr[0], a1 = xr[1];
            acc[0] += w*a0.x; acc[1] += w*a0.y; acc[2] += w*a0.z; acc[3] += w*a0.w;
            acc[4] += w*a1.x; acc[5] += w*a1.y; acc[6] += w*a1.z; acc[7] += w*a1.w;
        }
    }
    float bias = g_c1[o];
#pragma unroll
    for (int j = 0; j < 8; j++) {
        float v = acc[j] + bias;
        g_h[(b*PIX + pixbase + pg*8 + j)*HID + o] = v > 0.f ? v : 0.f;
    }
}

// ---------------- geometry helpers ----------------
__device__ __forceinline__ int upper_bound_sh(const float* a, int n, float v)
{
    int lo = 0, hi = n;
    while (lo < hi) {
        int m = (lo + hi) >> 1;
        if (a[m] <= v) lo = m + 1; else hi = m;
    }
    return lo;
}

__device__ __forceinline__ int computeBin(int wi, int row, int d,
                                          const float* cam, const float* in4,
                                          const float* radE, const float* angE)
{
    float u = (wi == FW-1) ? (float)(IW-1) : (float)((double)wi * ((double)(IW-1)/(FW-1)));
    float v = (row == FH-1) ? (float)(IH-1) : (float)((double)row * ((double)(IH-1)/(FH-1)));
    float dv = 1.0f + 0.5f * (float)d;
    float pcx = (u - in4[2]) * dv / in4[0];
    float pcy = (v - in4[3]) * dv / in4[1];
    float pcz = dv;
    float xl = cam[0]*pcx + cam[1]*pcy + cam[2]*pcz + cam[9];
    float yl = cam[3]*pcx + cam[4]*pcy + cam[5]*pcz + cam[10];
    float r  = sqrtf(xl*xl + yl*yl);
    float th = atan2f(yl, xl);
    int ri = upper_bound_sh(radE, NR+1, r)  - 1;
    int ti = upper_bound_sh(angE, NT+1, th) - 1;
    if (ri < 0 || ri >= NR || ti < 0 || ti >= NT) return -1;
    return ri*NT + ti;
}

// ---------------- K23: GEMM2 + BN + softmax + lift + scatter (block = one column) ----------------
__global__ void __launch_bounds__(256) k23_fused(const float* __restrict__ rots,
                                                 const float* __restrict__ trans,
                                                 const float* __restrict__ intr)
{
    __shared__ float vsh[32*VST];     // [row][depth 0..117 | pad | feat 120..199]
    __shared__ float uni[3776];       // phase1: hsh[pix*68+c]; phase2: wsum[h*32+row]
    __shared__ float radE[NR+1], angE[NT+1];
    __shared__ int   bins0[DEPTH];
    __shared__ int   headBin[DEPTH], headS[DEPTH], headE[DEPTH];
    __shared__ int   nheads, eqflag;
    __shared__ float cam[12];
    __shared__ float in4[4];

    int blk = blockIdx.x;             // 176 = 2 batches * 88 columns
    int b = blk / FW, wi = blk % FW;
    int t = threadIdx.x;

    for (int i = t; i < NR+1; i += 256) radE[i] = g_radE[i];
    for (int i = t; i < NT+1; i += 256) angE[i] = g_angE[i];
    if (t < 9) cam[t] = rots[b*9 + t];
    if (t < 3) cam[9+t] = trans[b*3 + t];
    if (t == 0) {
        in4[0] = intr[b*9 + 0]; in4[1] = intr[b*9 + 4];
        in4[2] = intr[b*9 + 2]; in4[3] = intr[b*9 + 5];
        nheads = 0;
        // bins are row-independent iff pcy never influences (xl, yl):
        // exact algebraic condition, replaces 31*118 runtime bin checks
        eqflag = (rots[b*9 + 1] == 0.f && rots[b*9 + 4] == 0.f) ? 1 : 0;
    }

    // load hidden for 32 rows of this column: hsh[pix*68 + c]
    float* hsh = uni;
    for (int i = t; i < 2048; i += 256) {
        int row = i >> 6, c = i & 63;
        hsh[row*68 + c] = g_h[(b*PIX + row*FW + wi)*HID + c];
    }
    __syncthreads();

    // GEMM2: 32 pixels x 198 outputs; hidden vector register-resident
    int pix = t & 31, og = t >> 5;
    float4 hreg[16];
    {
        const float4* hv = (const float4*)&hsh[pix*68];
#pragma unroll
        for (int i = 0; i < 16; i++) hreg[i] = hv[i];
    }
#pragma unroll
    for (int kk = 0; kk < 6; kk++) {
        int o0 = og + 32*kk;
        float a0=0.f, a1=0.f, a2=0.f, a3=0.f;
        const float4* wp0 = (const float4*)&g_w2f[(o0     )*HID];
        const float4* wp1 = (const float4*)&g_w2f[(o0 +  8)*HID];
        const float4* wp2 = (const float4*)&g_w2f[(o0 + 16)*HID];
        const float4* wp3 = (const float4*)&g_w2f[(o0 + 24)*HID];
#pragma unroll
        for (int c = 0; c < 16; c++) {
            float4 h = hreg[c];
            float4 w;
            w = wp0[c]; a0 += w.x*h.x + w.y*h.y + w.z*h.z + w.w*h.w;
            w = wp1[c]; a1 += w.x*h.x + w.y*h.y + w.z*h.z + w.w*h.w;
            w = wp2[c]; a2 += w.x*h.x + w.y*h.y + w.z*h.z + w.w*h.w;
            w = wp3[c]; a3 += w.x*h.x + w.y*h.y + w.z*h.z + w.w*h.w;
        }
        int s0 = o0      < DEPTH ? o0      : o0      + 2;
        int s1 = o0 + 8  < DEPTH ? o0 + 8  : o0 + 10;
        int s2 = o0 + 16 < DEPTH ? o0 + 16 : o0 + 18;
        int s3 = o0 + 24 < DEPTH ? o0 + 24 : o0 + 26;
        vsh[pix*VST + s0] = a0 + g_c2[o0];
        vsh[pix*VST + s1] = a1 + g_c2[o0+8];
        vsh[pix*VST + s2] = a2 + g_c2[o0+16];
        vsh[pix*VST + s3] = a3 + g_c2[o0+24];
    }
    if (og < 6) {
        int o = 192 + og;
        float a = 0.f;
        const float4* wp = (const float4*)&g_w2f[o*HID];
#pragma unroll
        for (int c = 0; c < 16; c++) {
            float4 h = hreg[c], w = wp[c];
            a += w.x*h.x + w.y*h.y + w.z*h.z + w.w*h.w;
        }
        vsh[pix*VST + o + 2] = a + g_c2[o];
    }
    __syncthreads();

    // softmax over first 118 channels, per pixel (warp handles 4 pixels)
    int lane = t & 31, warp = t >> 5;
    for (int j = 0; j < 4; j++) {
        int p = warp*4 + j;
        float a0 = vsh[p*VST + lane];
        float a1 = vsh[p*VST + lane + 32];
        float a2 = vsh[p*VST + lane + 64];
        float a3 = (lane + 96 < DEPTH) ? vsh[p*VST + lane + 96] : -INFINITY;
        float m = fmaxf(fmaxf(a0,a1), fmaxf(a2,a3));
#pragma unroll
        for (int s = 16; s; s >>= 1) m = fmaxf(m, __shfl_xor_sync(~0u, m, s));
        float e0 = expf(a0 - m), e1 = expf(a1 - m), e2 = expf(a2 - m);
        float e3 = (lane + 96 < DEPTH) ? expf(a3 - m) : 0.f;
        float sm = e0 + e1 + e2 + e3;
#pragma unroll
        for (int s = 16; s; s >>= 1) sm += __shfl_xor_sync(~0u, sm, s);
        float inv = 1.f / sm;
        vsh[p*VST + lane]      = e0*inv;
        vsh[p*VST + lane + 32] = e1*inv;
        vsh[p*VST + lane + 64] = e2*inv;
        if (lane + 96 < DEPTH) vsh[p*VST + lane + 96] = e3*inv;
    }
    __syncthreads();

    // bins for row 0 (row-independent when eqflag)
    if (t < DEPTH) bins0[t] = computeBin(wi, 0, t, cam, in4, radE, angE);
    __syncthreads();

    if (eqflag) {
        // run-compress row0 bins
        if (t < DEPTH) {
            int bn = bins0[t];
            if (bn >= 0 && (t == 0 || bins0[t-1] != bn)) {
                int k = t + 1;
                while (k < DEPTH && bins0[k] == bn) k++;
                int s = atomicAdd(&nheads, 1);
                headBin[s] = bn + b*NR*NT; headS[s] = t; headE[s] = k;
            }
        }
        __syncthreads();
        int nh = nheads;
        // per-head, per-row depth weight
        float* wsum = uni;   // hsh is dead
        for (int i = t; i < nh*32; i += 256) {
            int h = i >> 5, row = i & 31;
            float s = 0.f;
            for (int d = headS[h]; d < headE[h]; d++) s += vsh[row*VST + d];
            wsum[h*32 + row] = s;
        }
        __syncthreads();
        // aggregate 32 rows; 2 heads per thread so each feat read serves 8 FMA
        int npair = (nh + 1) >> 1;
        for (int i = t; i < npair*20; i += 256) {
            int hp = i/20, q = i - hp*20;
            int h0 = hp*2, h1 = h0 + 1;
            bool two = (h1 < nh);
            float4 A = make_float4(0.f,0.f,0.f,0.f);
            float4 Bv = make_float4(0.f,0.f,0.f,0.f);
#pragma unroll 4
            for (int row = 0; row < 32; row++) {
                float4 f = *(const float4*)&vsh[row*VST + FOFF + q*4];
                float w0 = wsum[h0*32 + row];
                A.x += w0*f.x; A.y += w0*f.y; A.z += w0*f.z; A.w += w0*f.w;
                if (two) {
                    float w1 = wsum[h1*32 + row];
                    Bv.x += w1*f.x; Bv.y += w1*f.y; Bv.z += w1*f.z; Bv.w += w1*f.w;
                }
            }
            float4* p0 = (float4*)&g_bev[headBin[h0]*C_OUT + q*4];
            asm volatile("red.global.add.v4.f32 [%0], {%1,%2,%3,%4};"
                         :: "l"(p0), "f"(A.x), "f"(A.y), "f"(A.z), "f"(A.w) : "memory");
            if (two) {
                float4* p1 = (float4*)&g_bev[headBin[h1]*C_OUT + q*4];
                asm volatile("red.global.add.v4.f32 [%0], {%1,%2,%3,%4};"
                             :: "l"(p1), "f"(Bv.x), "f"(Bv.y), "f"(Bv.z), "f"(Bv.w) : "memory");
            }
        }
    } else {
        // generic fallback: per-row scatter
        for (int row = 0; row < 32; row++) {
            __syncthreads();
            if (t == 0) nheads = 0;
            __syncthreads();
            if (t < DEPTH) bins0[t] = computeBin(wi, row, t, cam, in4, radE, angE);
            __syncthreads();
            if (t < DEPTH) {
                int bn = bins0[t];
                if (bn >= 0 && (t == 0 || bins0[t-1] != bn)) {
                    int k = t + 1;
                    while (k < DEPTH && bins0[k] == bn) k++;
                    float s = 0.f;
                    for (int d = t; d < k; d++) s += vsh[row*VST + d];
                    int sN = atomicAdd(&nheads, 1);
                    headBin[sN] = bn + b*NR*NT;
                    headS[sN] = __float_as_int(s);
                }
            }
            __syncthreads();
            int nh = nheads;
            for (int i = t; i < nh*20; i += 256) {
                int h = i/20, q = i - h*20;
                float w = __int_as_float(headS[h]);
                const float* f = &vsh[row*VST + FOFF + q*4];
                float4* pdst = (float4*)&g_bev[headBin[h]*C_OUT + q*4];
                asm volatile("red.global.add.v4.f32 [%0], {%1,%2,%3,%4};"
                             :: "l"(pdst), "f"(w*f[0]), "f"(w*f[1]), "f"(w*f[2]), "f"(w*f[3]) : "memory");
            }
        }
    }
}

// ---------------- K4: transpose [b][rt][c] -> out [b][c][rt], float4 both sides ----------------
__global__ void __launch_bounds__(256) k4_transpose(float* __restrict__ out)
{
    __shared__ float tile[32*81];
    int blk = blockIdx.x;               // 2048 = 2 * 1024
    int b   = blk >> 10;
    int rt0 = (blk & 1023) * 32;
    int t = threadIdx.x;

    // load: 32 rows x 20 float4 (channels)
#pragma unroll
    for (int i = 0; i < 3; i++) {
        int j = t + i*256;
        if (j < 640) {
            int r = j / 20, q = j - r*20;
            float4 f = *(const float4*)&g_bev[(b*(NR*NT) + rt0 + r)*C_OUT + q*4];
            float* tp = &tile[r*81 + q*4];
            tp[0] = f.x; tp[1] = f.y; tp[2] = f.z; tp[3] = f.w;
        }
    }
    __syncthreads();

    // store: 80 channels x 8 float4 (rt)
#pragma unroll
    for (int i = 0; i < 3; i++) {
        int j = t + i*256;
        if (j < 640) {
            int c = j >> 3, rt4 = j & 7;
            float4 f;
            f.x = tile[(rt4*4+0)*81 + c];
            f.y = tile[(rt4*4+1)*81 + c];
            f.z = tile[(rt4*4+2)*81 + c];
            f.w = tile[(rt4*4+3)*81 + c];
            *(float4*)&out[(b*C_OUT + c)*(NR*NT) + rt0 + rt4*4] = f;
        }
    }
}

// ---------------- launch ----------------
extern "C" void kernel_launch(void* const* d_in, const int* in_sizes, int n_in,
                              void* d_out, int out_size)
{
    const float* x     = (const float*)d_in[0];
    const float* rots  = (const float*)d_in[1];
    const float* trans = (const float*)d_in[2];
    const float* intr  = (const float*)d_in[3];
    const float* w1    = (const float*)d_in[4];
    const float* b1    = (const float*)d_in[5];
    const float* g1    = (const float*)d_in[6];
    const float* be1   = (const float*)d_in[7];
    const float* m1    = (const float*)d_in[8];
    const float* v1    = (const float*)d_in[9];
    const float* w2    = (const float*)d_in[10];
    const float* b2    = (const float*)d_in[11];
    const float* g2    = (const float*)d_in[12];
    const float* be2   = (const float*)d_in[13];
    const float* m2    = (const float*)d_in[14];
    const float* v2    = (const float*)d_in[15];
    float* out = (float*)d_out;

    kprep<<<1024, 256>>>(w1, b1, g1, be1, m1, v1, w2, b2, g2, be2, m2, v2);
    k1_gemm1<<<176, 256>>>(x);
    k23_fused<<<176, 256>>>(rots, trans, intr);
    k4_transpose<<<2048, 256>>>(out);
}

// round 4
// speedup vs baseline: 2.3196x; 1.0148x over previous
#include <cuda_runtime.h>
#include <math.h>

#define IH 256
#define IW 704
#define FH 32
#define FW 88
#define PIX (FH*FW)          // 2816
#define BATCH 2
#define C_IN 256
#define HID 64
#define DEPTH 118
#define C_OUT 80
#define OUT2 (DEPTH + C_OUT) // 198
#define NR 128
#define NT 256
#define PI_D 3.141592653589793
#define VST 204              // vsh row stride (float4 aligned; feat at +120)
#define FOFF 120

typedef unsigned long long u64;

// ---------------- device scratch ----------------
__device__ float g_h[BATCH*PIX*HID];                     // [b][pix][hid]
__device__ __align__(16) float g_bev[BATCH*NR*NT*C_OUT]; // [bin][80]

// ---------------- f32x2 helpers ----------------
__device__ __forceinline__ void fma2(u64& d, u64 a, u64 b) {
    asm("fma.rn.f32x2 %0, %1, %2, %3;" : "=l"(d) : "l"(a), "l"(b), "l"(d));
}
__device__ __forceinline__ u64 dup2(float v) {
    u64 r; asm("mov.b64 %0, {%1,%1};" : "=l"(r) : "f"(v)); return r;
}
__device__ __forceinline__ float2 unpack2(u64 v) {
    float2 r; asm("mov.b64 {%0,%1}, %2;" : "=f"(r.x), "=f"(r.y) : "l"(v)); return r;
}

// ---------------- K1: GEMM1 (256->64, BN folded) + ReLU; extra blocks zero g_bev ----------------
// blocks 0..175: GEMM (32 pixels each). blocks 176..303: zero g_bev slices.
__global__ void __launch_bounds__(256) k1_gemm1(const float* __restrict__ x,
                                                const float* __restrict__ w1,
                                                const float* __restrict__ b1,
                                                const float* __restrict__ g1,
                                                const float* __restrict__ be1,
                                                const float* __restrict__ m1,
                                                const float* __restrict__ v1)
{
    __shared__ float xs[64*32];
    __shared__ u64   ws2[64*65];
    __shared__ float inv1sh[64];

    int blk = blockIdx.x, t = threadIdx.x;

    if (blk >= 176) {
        // zero g_bev: 1310720 float4 over 128 blocks
        int base = (blk - 176) * 10240;
        float4 z = make_float4(0.f,0.f,0.f,0.f);
#pragma unroll 4
        for (int i = t; i < 10240; i += 256)
            ((float4*)g_bev)[base + i] = z;
        return;
    }

    int b = blk / 88;
    int pixbase = (blk % 88) * 32;
    int ot = t & 31;            // outputs ot and ot+32
    int pg = t >> 5;            // pixel group 0..7 (4 pixels)

    if (t < 64) inv1sh[t] = g1[t] / sqrtf(v1[t] + 1e-5f);

    u64 aA0 = 0, aA1 = 0, aB0 = 0, aB1 = 0;

    for (int cc = 0; cc < 4; cc++) {
        __syncthreads();
        // stage x tile: 512 float4 (64c x 8 float4)
#pragma unroll
        for (int i = 0; i < 2; i++) {
            int j = t + i*256;
            int c = j >> 3, p4 = j & 7;
            ((float4*)xs)[j] = ((const float4*)(x + (b*C_IN + cc*64 + c)*PIX + pixbase))[p4];
        }
        // stage w1 tile transposed+scaled+duplicated: 1024 float4
#pragma unroll
        for (int i = 0; i < 4; i++) {
            int j = t + i*256;
            int o_ = j >> 4, k4 = j & 15;
            float4 w = *(const float4*)(w1 + o_*C_IN + cc*64 + k4*4);
            float s = inv1sh[o_];
            ws2[(k4*4+0)*65 + o_] = dup2(w.x * s);
            ws2[(k4*4+1)*65 + o_] = dup2(w.y * s);
            ws2[(k4*4+2)*65 + o_] = dup2(w.z * s);
            ws2[(k4*4+3)*65 + o_] = dup2(w.w * s);
        }
        __syncthreads();
#pragma unroll 8
        for (int cl = 0; cl < 64; cl++) {
            u64 wa = ws2[cl*65 + ot];
            u64 wb = ws2[cl*65 + ot + 32];
            ulonglong2 xv = *(const ulonglong2*)&xs[cl*32 + pg*4];
            fma2(aA0, wa, xv.x); fma2(aA1, wa, xv.y);
            fma2(aB0, wb, xv.x); fma2(aB1, wb, xv.y);
        }
    }
    float invA = inv1sh[ot], invB = inv1sh[ot+32];
    float biasA = b1[ot]*invA + be1[ot] - m1[ot]*invA;
    float biasB = b1[ot+32]*invB + be1[ot+32] - m1[ot+32]*invB;
    float2 pA0 = unpack2(aA0), pA1 = unpack2(aA1);
    float2 pB0 = unpack2(aB0), pB1 = unpack2(aB1);
    int pbase = b*PIX + pixbase + pg*4;
    g_h[(pbase+0)*HID + ot]    = fmaxf(pA0.x + biasA, 0.f);
    g_h[(pbase+1)*HID + ot]    = fmaxf(pA0.y + biasA, 0.f);
    g_h[(pbase+2)*HID + ot]    = fmaxf(pA1.x + biasA, 0.f);
    g_h[(pbase+3)*HID + ot]    = fmaxf(pA1.y + biasA, 0.f);
    g_h[(pbase+0)*HID + ot+32] = fmaxf(pB0.x + biasB, 0.f);
    g_h[(pbase+1)*HID + ot+32] = fmaxf(pB0.y + biasB, 0.f);
    g_h[(pbase+2)*HID + ot+32] = fmaxf(pB1.x + biasB, 0.f);
    g_h[(pbase+3)*HID + ot+32] = fmaxf(pB1.y + biasB, 0.f);
}

// ---------------- geometry helpers ----------------
__device__ __forceinline__ int upper_bound_sh(const float* a, int n, float v)
{
    int lo = 0, hi = n;
    while (lo < hi) {
        int m = (lo + hi) >> 1;
        if (a[m] <= v) lo = m + 1; else hi = m;
    }
    return lo;
}

__device__ __forceinline__ int computeBin(int wi, int row, int d,
                                          const float* cam, const float* in4,
                                          const float* radE, const float* angE)
{
    float u = (wi == FW-1) ? (float)(IW-1) : (float)((double)wi * ((double)(IW-1)/(FW-1)));
    float v = (row == FH-1) ? (float)(IH-1) : (float)((double)row * ((double)(IH-1)/(FH-1)));
    float dv = 1.0f + 0.5f * (float)d;
    float pcx = (u - in4[2]) * dv / in4[0];
    float pcy = (v - in4[3]) * dv / in4[1];
    float pcz = dv;
    float xl = cam[0]*pcx + cam[1]*pcy + cam[2]*pcz + cam[9];
    float yl = cam[3]*pcx + cam[4]*pcy + cam[5]*pcz + cam[10];
    float r  = sqrtf(xl*xl + yl*yl);
    float th = atan2f(yl, xl);
    int ri = upper_bound_sh(radE, NR+1, r)  - 1;
    int ti = upper_bound_sh(angE, NT+1, th) - 1;
    if (ri < 0 || ri >= NR || ti < 0 || ti >= NT) return -1;
    return ri*NT + ti;
}

// dynamic smem layout (floats)
#define SM_W2S   0                 // 12672
#define SM_C2S   12672             // 200
#define SM_VSH   12872             // 32*204 = 6528
#define SM_UNI   19400             // 3776
#define SM_RADE  23176             // 132
#define SM_ANGE  23308             // 260
#define SM_BINS  23568             // 120 (int)
#define SM_HB    23688             // 120
#define SM_HS    23808             // 120
#define SM_HE    23928             // 120
#define SM_CAM   24048             // 12
#define SM_IN4   24060             // 4
#define SM_SCAL  24064             // 4 ints
#define K23_FLOATS 24068
#define K23_SMEM (K23_FLOATS*4)

// ---------------- K23: GEMM2 + BN + softmax + lift + scatter (block = one column) ----------------
__global__ void __launch_bounds__(512, 1) k23_fused(const float* __restrict__ rots,
                                                    const float* __restrict__ trans,
                                                    const float* __restrict__ intr,
                                                    const float* __restrict__ w2g,
                                                    const float* __restrict__ b2,
                                                    const float* __restrict__ g2,
                                                    const float* __restrict__ be2,
                                                    const float* __restrict__ m2,
                                                    const float* __restrict__ v2)
{
    extern __shared__ float smem[];
    float* w2s  = smem + SM_W2S;
    float* c2s  = smem + SM_C2S;
    float* vsh  = smem + SM_VSH;
    float* uni  = smem + SM_UNI;
    float* radE = smem + SM_RADE;
    float* angE = smem + SM_ANGE;
    int*   bins0   = (int*)(smem + SM_BINS);
    int*   headBin = (int*)(smem + SM_HB);
    int*   headS   = (int*)(smem + SM_HS);
    int*   headE   = (int*)(smem + SM_HE);
    float* cam  = smem + SM_CAM;
    float* in4  = smem + SM_IN4;
    int*   scal = (int*)(smem + SM_SCAL);   // [0]=nheads [1]=eqflag

    int blk = blockIdx.x;             // 176 = 2 batches * 88 columns
    int b = blk / FW, wi = blk % FW;
    int t = threadIdx.x;

    // edge tables (double precision, matches numpy)
    for (int i = t; i <= NR; i += 512) {
        double tt = (double)i * (1.0/128.0);
        radE[i] = (float)(1.0 + pow(tt, 1.5) * 59.0);
    }
    for (int i = t; i <= NT; i += 512) {
        double a = (i == NT) ? (PI_D*0.5) : (-PI_D*0.5 + (double)i * (PI_D/256.0));
        angE[i] = (float)a;
    }
    if (t < 9) cam[t] = rots[b*9 + t];
    if (t < 3) cam[9+t] = trans[b*3 + t];
    if (t == 0) {
        in4[0] = intr[b*9 + 0]; in4[1] = intr[b*9 + 4];
        in4[2] = intr[b*9 + 2]; in4[3] = intr[b*9 + 5];
        scal[0] = 0;
        scal[1] = (rots[b*9 + 1] == 0.f && rots[b*9 + 4] == 0.f) ? 1 : 0;
    }

    // stage w2 (BN-folded) into smem: 3168 float4
    for (int j = t; j < 3168; j += 512) {
        int o = j >> 4;
        float inv = g2[o] / sqrtf(v2[o] + 1e-5f);
        float4 w = ((const float4*)w2g)[j];
        w.x *= inv; w.y *= inv; w.z *= inv; w.w *= inv;
        ((float4*)w2s)[j] = w;
    }
    if (t < OUT2) {
        float inv = g2[t] / sqrtf(v2[t] + 1e-5f);
        c2s[t] = b2[t]*inv + be2[t] - m2[t]*inv;
    }

    // load hidden for 32 rows of this column: hsh[pix*68 + c]
    float* hsh = uni;
    for (int j = t; j < 512; j += 512) {
        int row = j >> 4, c4 = j & 15;
        ((float4*)&hsh[row*68])[c4] = ((const float4*)&g_h[(b*PIX + row*FW + wi)*HID])[c4];
    }
    __syncthreads();

    // GEMM2: 32 pixels x 198 outputs, f32x2
    int pix = t & 31, og = t >> 5;     // og 0..15
    u64 hh[32];
    {
        const ulonglong2* hv = (const ulonglong2*)&hsh[pix*68];
#pragma unroll
        for (int i = 0; i < 16; i++) { ulonglong2 p = hv[i]; hh[2*i] = p.x; hh[2*i+1] = p.y; }
    }
#pragma unroll
    for (int k = 0; k < 12; k++) {
        int o = og + 16*k;
        const ulonglong2* wp = (const ulonglong2*)&w2s[o*HID];
        u64 acc = 0;
#pragma unroll
        for (int c4 = 0; c4 < 16; c4++) {
            ulonglong2 wv = wp[c4];
            fma2(acc, wv.x, hh[2*c4]);
            fma2(acc, wv.y, hh[2*c4+1]);
        }
        float2 p = unpack2(acc);
        int s = (o < DEPTH) ? o : o + 2;
        vsh[pix*VST + s] = p.x + p.y + c2s[o];
    }
    if (og < 6) {
        int o = 192 + og;
        const ulonglong2* wp = (const ulonglong2*)&w2s[o*HID];
        u64 acc = 0;
#pragma unroll
        for (int c4 = 0; c4 < 16; c4++) {
            ulonglong2 wv = wp[c4];
            fma2(acc, wv.x, hh[2*c4]);
            fma2(acc, wv.y, hh[2*c4+1]);
        }
        float2 p = unpack2(acc);
        vsh[pix*VST + o + 2] = p.x + p.y + c2s[o];
    }
    __syncthreads();

    // softmax over first 118 channels; 16 warps, 2 pixels each
    int lane = t & 31, warp = t >> 5;
#pragma unroll
    for (int j = 0; j < 2; j++) {
        int p = warp*2 + j;
        float a0 = vsh[p*VST + lane];
        float a1 = vsh[p*VST + lane + 32];
        float a2 = vsh[p*VST + lane + 64];
        float a3 = (lane + 96 < DEPTH) ? vsh[p*VST + lane + 96] : -INFINITY;
        float m = fmaxf(fmaxf(a0,a1), fmaxf(a2,a3));
#pragma unroll
        for (int s = 16; s; s >>= 1) m = fmaxf(m, __shfl_xor_sync(~0u, m, s));
        float e0 = expf(a0 - m), e1 = expf(a1 - m), e2 = expf(a2 - m);
        float e3 = (lane + 96 < DEPTH) ? expf(a3 - m) : 0.f;
        float sm = e0 + e1 + e2 + e3;
#pragma unroll
        for (int s = 16; s; s >>= 1) sm += __shfl_xor_sync(~0u, sm, s);
        float inv = 1.f / sm;
        vsh[p*VST + lane]      = e0*inv;
        vsh[p*VST + lane + 32] = e1*inv;
        vsh[p*VST + lane + 64] = e2*inv;
        if (lane + 96 < DEPTH) vsh[p*VST + lane + 96] = e3*inv;
    }
    __syncthreads();

    // bins for row 0 (row-independent when eqflag)
    if (t < DEPTH) bins0[t] = computeBin(wi, 0, t, cam, in4, radE, angE);
    __syncthreads();

    if (scal[1]) {
        // run-compress row0 bins
        if (t < DEPTH) {
            int bn = bins0[t];
            if (bn >= 0 && (t == 0 || bins0[t-1] != bn)) {
                int k = t + 1;
                while (k < DEPTH && bins0[k] == bn) k++;
                int s = atomicAdd(&scal[0], 1);
                headBin[s] = bn + b*NR*NT; headS[s] = t; headE[s] = k;
            }
        }
        __syncthreads();
        int nh = scal[0];
        // per-head, per-row depth weight
        float* wsum = uni;   // hsh dead
        for (int i = t; i < nh*32; i += 512) {
            int h = i >> 5, row = i & 31;
            float s = 0.f;
            for (int d = headS[h]; d < headE[h]; d++) s += vsh[row*VST + d];
            wsum[h*32 + row] = s;
        }
        __syncthreads();
        // aggregate 32 rows; 2 heads per thread
        int npair = (nh + 1) >> 1;
        for (int i = t; i < npair*20; i += 512) {
            int hp = i/20, q = i - hp*20;
            int h0 = hp*2, h1 = h0 + 1;
            bool two = (h1 < nh);
            float4 A = make_float4(0.f,0.f,0.f,0.f);
            float4 Bv = make_float4(0.f,0.f,0.f,0.f);
#pragma unroll 4
            for (int row = 0; row < 32; row++) {
                float4 f = *(const float4*)&vsh[row*VST + FOFF + q*4];
                float w0 = wsum[h0*32 + row];
                A.x += w0*f.x; A.y += w0*f.y; A.z += w0*f.z; A.w += w0*f.w;
                if (two) {
                    float w1 = wsum[h1*32 + row];
                    Bv.x += w1*f.x; Bv.y += w1*f.y; Bv.z += w1*f.z; Bv.w += w1*f.w;
                }
            }
            float4* p0 = (float4*)&g_bev[headBin[h0]*C_OUT + q*4];
            asm volatile("red.global.add.v4.f32 [%0], {%1,%2,%3,%4};"
                         :: "l"(p0), "f"(A.x), "f"(A.y), "f"(A.z), "f"(A.w) : "memory");
            if (two) {
                float4* p1 = (float4*)&g_bev[headBin[h1]*C_OUT + q*4];
                asm volatile("red.global.add.v4.f32 [%0], {%1,%2,%3,%4};"
                             :: "l"(p1), "f"(Bv.x), "f"(Bv.y), "f"(Bv.z), "f"(Bv.w) : "memory");
            }
        }
    } else {
        // generic fallback: per-row scatter
        for (int row = 0; row < 32; row++) {
            __syncthreads();
            if (t == 0) scal[0] = 0;
            __syncthreads();
            if (t < DEPTH) bins0[t] = computeBin(wi, row, t, cam, in4, radE, angE);
            __syncthreads();
            if (t < DEPTH) {
                int bn = bins0[t];
                if (bn >= 0 && (t == 0 || bins0[t-1] != bn)) {
                    int k = t + 1;
                    while (k < DEPTH && bins0[k] == bn) k++;
                    float s = 0.f;
                    for (int d = t; d < k; d++) s += vsh[row*VST + d];
                    int sN = atomicAdd(&scal[0], 1);
                    headBin[sN] = bn + b*NR*NT;
                    headS[sN] = __float_as_int(s);
                }
            }
            __syncthreads();
            int nh = scal[0];
            for (int i = t; i < nh*20; i += 512) {
                int h = i/20, q = i - h*20;
                float w = __int_as_float(headS[h]);
                const float* f = &vsh[row*VST + FOFF + q*4];
                float4* pdst = (float4*)&g_bev[headBin[h]*C_OUT + q*4];
                asm volatile("red.global.add.v4.f32 [%0], {%1,%2,%3,%4};"
                             :: "l"(pdst), "f"(w*f[0]), "f"(w*f[1]), "f"(w*f[2]), "f"(w*f[3]) : "memory");
            }
        }
    }
}

// ---------------- K4: transpose [b][rt][c] -> out [b][c][rt], double-buffered 4 tiles/block ----------------
__global__ void __launch_bounds__(256) k4_transpose(float* __restrict__ out)
{
    __shared__ float tile[2][32*81];
    int blk = blockIdx.x;               // 512 = 2 * 256
    int b   = blk >> 8;
    int grp = blk & 255;                // 128 rt rows per group
    int t = threadIdx.x;

    // load tile 0
    {
        int rt0 = grp*128;
#pragma unroll
        for (int i = 0; i < 3; i++) {
            int j = t + i*256;
            if (j < 640) {
                int r = j / 20, q = j - r*20;
                float4 f = *(const float4*)&g_bev[(b*(NR*NT) + rt0 + r)*C_OUT + q*4];
                float* tp = &tile[0][r*81 + q*4];
                tp[0] = f.x; tp[1] = f.y; tp[2] = f.z; tp[3] = f.w;
            }
        }
    }
    __syncthreads();

#pragma unroll
    for (int it = 0; it < 4; it++) {
        int cur = it & 1;
        if (it < 3) {
            int rt0 = grp*128 + (it+1)*32;
#pragma unroll
            for (int i = 0; i < 3; i++) {
                int j = t + i*256;
                if (j < 640) {
                    int r = j / 20, q = j - r*20;
                    float4 f = *(const float4*)&g_bev[(b*(NR*NT) + rt0 + r)*C_OUT + q*4];
                    float* tp = &tile[1-cur][r*81 + q*4];
                    tp[0] = f.x; tp[1] = f.y; tp[2] = f.z; tp[3] = f.w;
                }
            }
        }
        int rt0 = grp*128 + it*32;
#pragma unroll
        for (int i = 0; i < 3; i++) {
            int j = t + i*256;
            if (j < 640) {
                int c = j >> 3, rt4 = j & 7;
                float4 f;
                f.x = tile[cur][(rt4*4+0)*81 + c];
                f.y = tile[cur][(rt4*4+1)*81 + c];
                f.z = tile[cur][(rt4*4+2)*81 + c];
                f.w = tile[cur][(rt4*4+3)*81 + c];
                *(float4*)&out[(b*C_OUT + c)*(NR*NT) + rt0 + rt4*4] = f;
            }
        }
        __syncthreads();
    }
}

// ---------------- launch ----------------
extern "C" void kernel_launch(void* const* d_in, const int* in_sizes, int n_in,
                              void* d_out, int out_size)
{
    const float* x     = (const float*)d_in[0];
    const float* rots  = (const float*)d_in[1];
    const float* trans = (const float*)d_in[2];
    const float* intr  = (const float*)d_in[3];
    const float* w1    = (const float*)d_in[4];
    const float* b1    = (const float*)d_in[5];
    const float* g1    = (const float*)d_in[6];
    const float* be1   = (const float*)d_in[7];
    const float* m1    = (const float*)d_in[8];
    const float* v1    = (const float*)d_in[9];
    const float* w2    = (const float*)d_in[10];
    const float* b2    = (const float*)d_in[11];
    const float* g2    = (const float*)d_in[12];
    const float* be2   = (const float*)d_in[13];
    const float* m2    = (const float*)d_in[14];
    const float* v2    = (const float*)d_in[15];
    float* out = (float*)d_out;

    static int configured = 0;
    if (!configured) {
        cudaFuncSetAttribute(k23_fused, cudaFuncAttributeMaxDynamicSharedMemorySize, K23_SMEM);
        configured = 1;
    }

    k1_gemm1<<<304, 256>>>(x, w1, b1, g1, be1, m1, v1);
    k23_fused<<<176, 512, K23_SMEM>>>(rots, trans, intr, w2, b2, g2, be2, m2, v2);
    k4_transpose<<<512, 256>>>(out);
}

// round 5
// speedup vs baseline: 2.5447x; 1.0971x over previous
#include <cuda_runtime.h>
#include <math.h>

#define IH 256
#define IW 704
#define FH 32
#define FW 88
#define PIX (FH*FW)          // 2816
#define BATCH 2
#define C_IN 256
#define HID 64
#define DEPTH 118
#define C_OUT 80
#define OUT2 (DEPTH + C_OUT) // 198
#define NR 128
#define NT 256
#define NRT (NR*NT)          // 32768
#define PI_D 3.141592653589793
#define VST 204              // vsh row stride (float4 aligned; feat at +120)
#define FOFF 120

typedef unsigned long long u64;

// ---------------- device scratch ----------------
__device__ float g_h[BATCH*PIX*HID];                     // [b][pix][hid]

// ---------------- f32x2 helpers ----------------
__device__ __forceinline__ void fma2(u64& d, u64 a, u64 b) {
    asm("fma.rn.f32x2 %0, %1, %2, %3;" : "=l"(d) : "l"(a), "l"(b), "l"(d));
}
__device__ __forceinline__ float2 unpack2(u64 v) {
    float2 r; asm("mov.b64 {%0,%1}, %2;" : "=f"(r.x), "=f"(r.y) : "l"(v)); return r;
}
__device__ __forceinline__ void redadd(float* p, float v) {
    asm volatile("red.global.add.f32 [%0], %1;" :: "l"(p), "f"(v) : "memory");
}

// ---------------- K1: GEMM1 (256->64) + BN(epilogue) + ReLU; extra blocks zero d_out ----------
// blocks 0..351: GEMM (16 pixels each). blocks 352..479: zero out (5.24M floats).
__global__ void __launch_bounds__(256) k1_gemm1(const float* __restrict__ x,
                                                const float* __restrict__ w1,
                                                const float* __restrict__ b1,
                                                const float* __restrict__ g1,
                                                const float* __restrict__ be1,
                                                const float* __restrict__ m1,
                                                const float* __restrict__ v1,
                                                float* __restrict__ outz)
{
    __shared__ float xs[64*16];      // [c][pix]
    __shared__ float ws[64*65];      // [c][o], stride 65

    int blk = blockIdx.x, t = threadIdx.x;

    if (blk >= 352) {
        // zero d_out: 1,310,720 float4 over 128 blocks
        int base = (blk - 352) * 10240;
        float4 z = make_float4(0.f,0.f,0.f,0.f);
#pragma unroll 4
        for (int i = t; i < 10240; i += 256)
            ((float4*)outz)[base + i] = z;
        return;
    }

    int b = blk / 176;
    int pixbase = (blk % 176) * 16;
    int o  = t & 63;            // output channel
    int pg = t >> 6;            // pixel group 0..3 (4 pixels each)

    float4 acc = make_float4(0.f,0.f,0.f,0.f);

    for (int cc = 0; cc < 4; cc++) {
        __syncthreads();
        // stage x tile: 256 float4 (64c x 4 float4)
        {
            int c = t >> 2, p4 = t & 3;
            ((float4*)xs)[t] = ((const float4*)(x + (b*C_IN + cc*64 + c)*PIX + pixbase))[p4];
        }
        // stage w1 tile transposed: 64o x 64c, 16 floats/thread
#pragma unroll
        for (int i = 0; i < 4; i++) {
            int j = t + i*256;
            int oo = j >> 4, k4 = j & 15;
            float4 w = *(const float4*)(w1 + oo*C_IN + cc*64 + k4*4);
            ws[(k4*4+0)*65 + oo] = w.x;
            ws[(k4*4+1)*65 + oo] = w.y;
            ws[(k4*4+2)*65 + oo] = w.z;
            ws[(k4*4+3)*65 + oo] = w.w;
        }
        __syncthreads();
#pragma unroll 8
        for (int cl = 0; cl < 64; cl++) {
            float w = ws[cl*65 + o];
            float4 xv = *(const float4*)&xs[cl*16 + pg*4];
            acc.x += w*xv.x; acc.y += w*xv.y; acc.z += w*xv.z; acc.w += w*xv.w;
        }
    }
    // BN fold in epilogue (linear in acc)
    float inv  = g1[o] / sqrtf(v1[o] + 1e-5f);
    float bias = b1[o]*inv + be1[o] - m1[o]*inv;
    int pbase = b*PIX + pixbase + pg*4;
    g_h[(pbase+0)*HID + o] = fmaxf(acc.x*inv + bias, 0.f);
    g_h[(pbase+1)*HID + o] = fmaxf(acc.y*inv + bias, 0.f);
    g_h[(pbase+2)*HID + o] = fmaxf(acc.z*inv + bias, 0.f);
    g_h[(pbase+3)*HID + o] = fmaxf(acc.w*inv + bias, 0.f);
}

// ---------------- geometry helpers ----------------
__device__ __forceinline__ int upper_bound_sh(const float* a, int n, float v)
{
    int lo = 0, hi = n;
    while (lo < hi) {
        int m = (lo + hi) >> 1;
        if (a[m] <= v) lo = m + 1; else hi = m;
    }
    return lo;
}

__device__ __forceinline__ int computeBin(int wi, int row, int d,
                                          const float* cam, const float* in4,
                                          const float* radE, const float* angE)
{
    float u = (wi == FW-1) ? (float)(IW-1) : (float)((double)wi * ((double)(IW-1)/(FW-1)));
    float v = (row == FH-1) ? (float)(IH-1) : (float)((double)row * ((double)(IH-1)/(FH-1)));
    float dv = 1.0f + 0.5f * (float)d;
    float pcx = (u - in4[2]) * dv / in4[0];
    float pcy = (v - in4[3]) * dv / in4[1];
    float pcz = dv;
    float xl = cam[0]*pcx + cam[1]*pcy + cam[2]*pcz + cam[9];
    float yl = cam[3]*pcx + cam[4]*pcy + cam[5]*pcz + cam[10];
    float r  = sqrtf(xl*xl + yl*yl);
    float th = atan2f(yl, xl);
    int ri = upper_bound_sh(radE, NR+1, r)  - 1;
    int ti = upper_bound_sh(angE, NT+1, th) - 1;
    if (ri < 0 || ri >= NR || ti < 0 || ti >= NT) return -1;
    return ri*NT + ti;
}

// dynamic smem layout (floats)
#define SM_W2S   0                 // 12672
#define SM_C2S   12672             // 200
#define SM_VSH   12872             // 32*204 = 6528
#define SM_UNI   19400             // 3776
#define SM_RADE  23176             // 132
#define SM_ANGE  23308             // 260
#define SM_BINS  23568             // 120 (int)
#define SM_HB    23688             // 120
#define SM_HS    23808             // 120
#define SM_HE    23928             // 120
#define SM_CAM   24048             // 12
#define SM_IN4   24060             // 4
#define SM_SCAL  24064             // 4 ints
#define K23_FLOATS 24068
#define K23_SMEM (K23_FLOATS*4)

// ---------------- K23: GEMM2 + BN + softmax + lift + scatter-to-output ----------------
__global__ void __launch_bounds__(512, 1) k23_fused(const float* __restrict__ rots,
                                                    const float* __restrict__ trans,
                                                    const float* __restrict__ intr,
                                                    const float* __restrict__ w2g,
                                                    const float* __restrict__ b2,
                                                    const float* __restrict__ g2,
                                                    const float* __restrict__ be2,
                                                    const float* __restrict__ m2,
                                                    const float* __restrict__ v2,
                                                    float* __restrict__ out)
{
    extern __shared__ float smem[];
    float* w2s  = smem + SM_W2S;
    float* c2s  = smem + SM_C2S;
    float* vsh  = smem + SM_VSH;
    float* uni  = smem + SM_UNI;
    float* radE = smem + SM_RADE;
    float* angE = smem + SM_ANGE;
    int*   bins0   = (int*)(smem + SM_BINS);
    int*   headBin = (int*)(smem + SM_HB);
    int*   headS   = (int*)(smem + SM_HS);
    int*   headE   = (int*)(smem + SM_HE);
    float* cam  = smem + SM_CAM;
    float* in4  = smem + SM_IN4;
    int*   scal = (int*)(smem + SM_SCAL);   // [0]=nheads [1]=eqflag

    int blk = blockIdx.x;             // 176 = 2 batches * 88 columns
    int b = blk / FW, wi = blk % FW;
    int t = threadIdx.x;

    // edge tables (double precision, matches numpy)
    for (int i = t; i <= NR; i += 512) {
        double tt = (double)i * (1.0/128.0);
        radE[i] = (float)(1.0 + pow(tt, 1.5) * 59.0);
    }
    for (int i = t; i <= NT; i += 512) {
        double a = (i == NT) ? (PI_D*0.5) : (-PI_D*0.5 + (double)i * (PI_D/256.0));
        angE[i] = (float)a;
    }
    if (t < 9) cam[t] = rots[b*9 + t];
    if (t < 3) cam[9+t] = trans[b*3 + t];
    if (t == 0) {
        in4[0] = intr[b*9 + 0]; in4[1] = intr[b*9 + 4];
        in4[2] = intr[b*9 + 2]; in4[3] = intr[b*9 + 5];
        scal[0] = 0;
        scal[1] = (rots[b*9 + 1] == 0.f && rots[b*9 + 4] == 0.f) ? 1 : 0;
    }

    // stage w2 (BN-folded) into smem: 3168 float4
    for (int j = t; j < 3168; j += 512) {
        int o = j >> 4;
        float inv = g2[o] / sqrtf(v2[o] + 1e-5f);
        float4 w = ((const float4*)w2g)[j];
        w.x *= inv; w.y *= inv; w.z *= inv; w.w *= inv;
        ((float4*)w2s)[j] = w;
    }
    if (t < OUT2) {
        float inv = g2[t] / sqrtf(v2[t] + 1e-5f);
        c2s[t] = b2[t]*inv + be2[t] - m2[t]*inv;
    }

    // load hidden for 32 rows of this column: hsh[pix*68 + c]
    float* hsh = uni;
    {
        int row = t >> 4, c4 = t & 15;
        if (t < 512)
            ((float4*)&hsh[row*68])[c4] = ((const float4*)&g_h[(b*PIX + row*FW + wi)*HID])[c4];
    }
    __syncthreads();

    // bins for row 0 (overlaps with GEMM2 below on other pipes)
    if (t < DEPTH) bins0[t] = computeBin(wi, 0, t, cam, in4, radE, angE);

    // GEMM2: 32 pixels x 198 outputs, f32x2
    int pix = t & 31, og = t >> 5;     // og 0..15
    u64 hh[32];
    {
        const ulonglong2* hv = (const ulonglong2*)&hsh[pix*68];
#pragma unroll
        for (int i = 0; i < 16; i++) { ulonglong2 p = hv[i]; hh[2*i] = p.x; hh[2*i+1] = p.y; }
    }
#pragma unroll
    for (int k = 0; k < 12; k++) {
        int o = og + 16*k;
        const ulonglong2* wp = (const ulonglong2*)&w2s[o*HID];
        u64 acc = 0;
#pragma unroll
        for (int c4 = 0; c4 < 16; c4++) {
            ulonglong2 wv = wp[c4];
            fma2(acc, wv.x, hh[2*c4]);
            fma2(acc, wv.y, hh[2*c4+1]);
        }
        float2 p = unpack2(acc);
        int s = (o < DEPTH) ? o : o + 2;
        vsh[pix*VST + s] = p.x + p.y + c2s[o];
    }
    if (og < 6) {
        int o = 192 + og;
        const ulonglong2* wp = (const ulonglong2*)&w2s[o*HID];
        u64 acc = 0;
#pragma unroll
        for (int c4 = 0; c4 < 16; c4++) {
            ulonglong2 wv = wp[c4];
            fma2(acc, wv.x, hh[2*c4]);
            fma2(acc, wv.y, hh[2*c4+1]);
        }
        float2 p = unpack2(acc);
        vsh[pix*VST + o + 2] = p.x + p.y + c2s[o];
    }
    __syncthreads();

    // softmax over first 118 channels; 16 warps, 2 pixels each
    int lane = t & 31, warp = t >> 5;
#pragma unroll
    for (int j = 0; j < 2; j++) {
        int p = warp*2 + j;
        float a0 = vsh[p*VST + lane];
        float a1 = vsh[p*VST + lane + 32];
        float a2 = vsh[p*VST + lane + 64];
        float a3 = (lane + 96 < DEPTH) ? vsh[p*VST + lane + 96] : -INFINITY;
        float m = fmaxf(fmaxf(a0,a1), fmaxf(a2,a3));
#pragma unroll
        for (int s = 16; s; s >>= 1) m = fmaxf(m, __shfl_xor_sync(~0u, m, s));
        float e0 = expf(a0 - m), e1 = expf(a1 - m), e2 = expf(a2 - m);
        float e3 = (lane + 96 < DEPTH) ? expf(a3 - m) : 0.f;
        float sm = e0 + e1 + e2 + e3;
#pragma unroll
        for (int s = 16; s; s >>= 1) sm += __shfl_xor_sync(~0u, sm, s);
        float inv = 1.f / sm;
        vsh[p*VST + lane]      = e0*inv;
        vsh[p*VST + lane + 32] = e1*inv;
        vsh[p*VST + lane + 64] = e2*inv;
        if (lane + 96 < DEPTH) vsh[p*VST + lane + 96] = e3*inv;
    }
    __syncthreads();

    float* outb = out + b*C_OUT*NRT;

    if (scal[1]) {
        // run-compress row0 bins (row-independent)
        if (t < DEPTH) {
            int bn = bins0[t];
            if (bn >= 0 && (t == 0 || bins0[t-1] != bn)) {
                int k = t + 1;
                while (k < DEPTH && bins0[k] == bn) k++;
                int s = atomicAdd(&scal[0], 1);
                headBin[s] = bn; headS[s] = t; headE[s] = k;
            }
        }
        __syncthreads();
        int nh = scal[0];
        // per-head, per-row depth weight
        float* wsum = uni;   // hsh dead
        for (int i = t; i < nh*32; i += 512) {
            int h = i >> 5, row = i & 31;
            float s = 0.f;
            for (int d = headS[h]; d < headE[h]; d++) s += vsh[row*VST + d];
            wsum[h*32 + row] = s;
        }
        __syncthreads();
        // aggregate 32 rows; 2 heads per thread; scatter scalar REDs to final layout
        int npair = (nh + 1) >> 1;
        for (int i = t; i < npair*20; i += 512) {
            int hp = i/20, q = i - hp*20;
            int h0 = hp*2, h1 = h0 + 1;
            bool two = (h1 < nh);
            float4 A = make_float4(0.f,0.f,0.f,0.f);
            float4 Bv = make_float4(0.f,0.f,0.f,0.f);
#pragma unroll 4
            for (int row = 0; row < 32; row++) {
                float4 f = *(const float4*)&vsh[row*VST + FOFF + q*4];
                float w0 = wsum[h0*32 + row];
                A.x += w0*f.x; A.y += w0*f.y; A.z += w0*f.z; A.w += w0*f.w;
                if (two) {
                    float w1 = wsum[h1*32 + row];
                    Bv.x += w1*f.x; Bv.y += w1*f.y; Bv.z += w1*f.z; Bv.w += w1*f.w;
                }
            }
            float* p0 = outb + (q*4)*NRT + headBin[h0];
            redadd(p0,          A.x);
            redadd(p0 +   NRT,  A.y);
            redadd(p0 + 2*NRT,  A.z);
            redadd(p0 + 3*NRT,  A.w);
            if (two) {
                float* p1 = outb + (q*4)*NRT + headBin[h1];
                redadd(p1,          Bv.x);
                redadd(p1 +   NRT,  Bv.y);
                redadd(p1 + 2*NRT,  Bv.z);
                redadd(p1 + 3*NRT,  Bv.w);
            }
        }
    } else {
        // generic fallback: per-row scatter
        for (int row = 0; row < 32; row++) {
            __syncthreads();
            if (t == 0) scal[0] = 0;
            __syncthreads();
            if (t < DEPTH) bins0[t] = computeBin(wi, row, t, cam, in4, radE, angE);
            __syncthreads();
            if (t < DEPTH) {
                int bn = bins0[t];
                if (bn >= 0 && (t == 0 || bins0[t-1] != bn)) {
                    int k = t + 1;
                    while (k < DEPTH && bins0[k] == bn) k++;
                    float s = 0.f;
                    for (int d = t; d < k; d++) s += vsh[row*VST + d];
                    int sN = atomicAdd(&scal[0], 1);
                    headBin[sN] = bn;
                    headS[sN] = __float_as_int(s);
                }
            }
            __syncthreads();
            int nh = scal[0];
            for (int i = t; i < nh*20; i += 512) {
                int h = i/20, q = i - h*20;
                float w = __int_as_float(headS[h]);
                const float* f = &vsh[row*VST + FOFF + q*4];
                float* p0 = outb + (q*4)*NRT + headBin[h];
                redadd(p0,          w*f[0]);
                redadd(p0 +   NRT,  w*f[1]);
                redadd(p0 + 2*NRT,  w*f[2]);
                redadd(p0 + 3*NRT,  w*f[3]);
            }
        }
    }
}

// ---------------- launch ----------------
extern "C" void kernel_launch(void* const* d_in, const int* in_sizes, int n_in,
                              void* d_out, int out_size)
{
    const float* x     = (const float*)d_in[0];
    const float* rots  = (const float*)d_in[1];
    const float* trans = (const float*)d_in[2];
    const float* intr  = (const float*)d_in[3];
    const float* w1    = (const float*)d_in[4];
    const float* b1    = (const float*)d_in[5];
    const float* g1    = (const float*)d_in[6];
    const float* be1   = (const float*)d_in[7];
    const float* m1    = (const float*)d_in[8];
    const float* v1    = (const float*)d_in[9];
    const float* w2    = (const float*)d_in[10];
    const float* b2    = (const float*)d_in[11];
    const float* g2    = (const float*)d_in[12];
    const float* be2   = (const float*)d_in[13];
    const float* m2    = (const float*)d_in[14];
    const float* v2    = (const float*)d_in[15];
    float* out = (float*)d_out;

    static int configured = 0;
    if (!configured) {
        cudaFuncSetAttribute(k23_fused, cudaFuncAttributeMaxDynamicSharedMemorySize, K23_SMEM);
        configured = 1;
    }

    k1_gemm1<<<480, 256>>>(x, w1, b1, g1, be1, m1, v1, out);
    k23_fused<<<176, 512, K23_SMEM>>>(rots, trans, intr, w2, b2, g2, be2, m2, v2, out);
}

// round 6
// speedup vs baseline: 3.1261x; 1.2285x over previous
#include <cuda_runtime.h>
#include <math.h>

#define IH 256
#define IW 704
#define FH 32
#define FW 88
#define PIX (FH*FW)          // 2816
#define BATCH 2
#define C_IN 256
#define HID 64
#define DEPTH 118
#define C_OUT 80
#define OUT2 (DEPTH + C_OUT) // 198
#define NR 128
#define NT 256
#define NRT (NR*NT)          // 32768
#define PI_D 3.141592653589793
#define VST 204              // vsh row stride (float4 aligned; feat at +120)
#define FOFF 120
#define HST 68               // hsh row stride

typedef unsigned long long u64;

// ---------------- device scratch ----------------
__device__ float g_h[BATCH*PIX*HID];         // [b][pix][hid]
__device__ __align__(16) float g_w2f[OUT2*HID];  // BN-folded w2
__device__ float g_c2[OUT2];
__device__ float g_radE[NR+1];
__device__ float g_angE[NT+1];

// ---------------- f32x2 helpers ----------------
__device__ __forceinline__ void fma2(u64& d, u64 a, u64 b) {
    asm("fma.rn.f32x2 %0, %1, %2, %3;" : "=l"(d) : "l"(a), "l"(b), "l"(d));
}
__device__ __forceinline__ float2 unpack2(u64 v) {
    float2 r; asm("mov.b64 {%0,%1}, %2;" : "=f"(r.x), "=f"(r.y) : "l"(v)); return r;
}
__device__ __forceinline__ void redadd(float* p, float v) {
    asm volatile("red.global.add.f32 [%0], %1;" :: "l"(p), "f"(v) : "memory");
}

// ---------------- K1: GEMM1 + zero d_out + precompute tables / folded w2 ----------------
// blocks 0..351: GEMM (16 pixels each). 352..479: zero d_out. 480: edges+c2. 481..488: fold w2.
__global__ void __launch_bounds__(256) k1_gemm1(const float* __restrict__ x,
                                                const float* __restrict__ w1,
                                                const float* __restrict__ b1,
                                                const float* __restrict__ g1,
                                                const float* __restrict__ be1,
                                                const float* __restrict__ m1,
                                                const float* __restrict__ v1,
                                                const float* __restrict__ w2,
                                                const float* __restrict__ b2,
                                                const float* __restrict__ g2,
                                                const float* __restrict__ be2,
                                                const float* __restrict__ m2,
                                                const float* __restrict__ v2,
                                                float* __restrict__ outz)
{
    __shared__ float xs[64*16];      // [c][pix]
    __shared__ float ws[64*65];      // [c][o], stride 65

    int blk = blockIdx.x, t = threadIdx.x;

    if (blk >= 352) {
        if (blk < 480) {
            // zero d_out: 1,310,720 float4 over 128 blocks
            int base = (blk - 352) * 10240;
            float4 z = make_float4(0.f,0.f,0.f,0.f);
#pragma unroll 4
            for (int i = t; i < 10240; i += 256)
                ((float4*)outz)[base + i] = z;
        } else if (blk == 480) {
            // edge tables (fp64, matches numpy) + folded c2
            if (t <= NR) {
                double tt = (double)t * (1.0/128.0);
                g_radE[t] = (float)(1.0 + pow(tt, 1.5) * 59.0);
            }
            for (int i = t; i <= NT; i += 256) {
                double a = (i == NT) ? (PI_D*0.5) : (-PI_D*0.5 + (double)i * (PI_D/256.0));
                g_angE[i] = (float)a;
            }
            if (t < OUT2) {
                float inv = g2[t] / sqrtf(v2[t] + 1e-5f);
                g_c2[t] = b2[t]*inv + be2[t] - m2[t]*inv;
            }
        } else {
            // fold w2: 3168 float4 over 8 blocks
            int base = (blk - 481) * 396;
            for (int j = base + t; j < base + 396; j += 256) {
                int o = j >> 4;
                float inv = g2[o] / sqrtf(v2[o] + 1e-5f);
                float4 w = ((const float4*)w2)[j];
                w.x *= inv; w.y *= inv; w.z *= inv; w.w *= inv;
                ((float4*)g_w2f)[j] = w;
            }
        }
        return;
    }

    int b = blk / 176;
    int pixbase = (blk % 176) * 16;
    int o  = t & 63;            // output channel
    int pg = t >> 6;            // pixel group 0..3 (4 pixels each)

    float4 acc = make_float4(0.f,0.f,0.f,0.f);

    for (int cc = 0; cc < 4; cc++) {
        __syncthreads();
        {
            int c = t >> 2, p4 = t & 3;
            ((float4*)xs)[t] = ((const float4*)(x + (b*C_IN + cc*64 + c)*PIX + pixbase))[p4];
        }
#pragma unroll
        for (int i = 0; i < 4; i++) {
            int j = t + i*256;
            int oo = j >> 4, k4 = j & 15;
            float4 w = *(const float4*)(w1 + oo*C_IN + cc*64 + k4*4);
            ws[(k4*4+0)*65 + oo] = w.x;
            ws[(k4*4+1)*65 + oo] = w.y;
            ws[(k4*4+2)*65 + oo] = w.z;
            ws[(k4*4+3)*65 + oo] = w.w;
        }
        __syncthreads();
#pragma unroll 8
        for (int cl = 0; cl < 64; cl++) {
            float w = ws[cl*65 + o];
            float4 xv = *(const float4*)&xs[cl*16 + pg*4];
            acc.x += w*xv.x; acc.y += w*xv.y; acc.z += w*xv.z; acc.w += w*xv.w;
        }
    }
    float inv  = g1[o] / sqrtf(v1[o] + 1e-5f);
    float bias = b1[o]*inv + be1[o] - m1[o]*inv;
    int pbase = b*PIX + pixbase + pg*4;
    g_h[(pbase+0)*HID + o] = fmaxf(acc.x*inv + bias, 0.f);
    g_h[(pbase+1)*HID + o] = fmaxf(acc.y*inv + bias, 0.f);
    g_h[(pbase+2)*HID + o] = fmaxf(acc.z*inv + bias, 0.f);
    g_h[(pbase+3)*HID + o] = fmaxf(acc.w*inv + bias, 0.f);
}

// ---------------- geometry helpers ----------------
__device__ __forceinline__ int upper_bound_sh(const float* a, int n, float v)
{
    int lo = 0, hi = n;
    while (lo < hi) {
        int m = (lo + hi) >> 1;
        if (a[m] <= v) lo = m + 1; else hi = m;
    }
    return lo;
}

__device__ __forceinline__ int computeBin(int wi, int row, int d,
                                          const float* cam, const float* in4,
                                          const float* radE, const float* angE)
{
    float u = (wi == FW-1) ? (float)(IW-1) : (float)((double)wi * ((double)(IW-1)/(FW-1)));
    float v = (row == FH-1) ? (float)(IH-1) : (float)((double)row * ((double)(IH-1)/(FH-1)));
    float dv = 1.0f + 0.5f * (float)d;
    float pcx = (u - in4[2]) * dv / in4[0];
    float pcy = (v - in4[3]) * dv / in4[1];
    float pcz = dv;
    float xl = cam[0]*pcx + cam[1]*pcy + cam[2]*pcz + cam[9];
    float yl = cam[3]*pcx + cam[4]*pcy + cam[5]*pcz + cam[10];
    float r  = sqrtf(xl*xl + yl*yl);
    float th = atan2f(yl, xl);
    int ri = upper_bound_sh(radE, NR+1, r)  - 1;
    int ti = upper_bound_sh(angE, NT+1, th) - 1;
    if (ri < 0 || ri >= NR || ti < 0 || ti >= NT) return -1;
    return ri*NT + ti;
}

// dynamic smem layout (floats)
#define SM_W2S   0                 // 12672
#define SM_C2S   12672             // 200
#define SM_VSH   12872             // 32*204 = 6528
#define SM_UNI   19400             // 32*68 = 2176 (hsh) / wsum
#define SM_RADE  23176             // 132
#define SM_ANGE  23308             // 260
#define SM_BINS  23568             // 120 (int)
#define SM_HB    23688             // 120
#define SM_HS    23808             // 120
#define SM_HE    23928             // 120
#define SM_CAM   24048             // 12
#define SM_IN4   24060             // 4
#define SM_SCAL  24064             // 4 ints
#define K23_FLOATS 24068
#define K23_SMEM (K23_FLOATS*4)

// ---------------- K23: GEMM2 + BN + softmax + lift + scatter-to-output ----------------
__global__ void __launch_bounds__(512, 2) k23_fused(const float* __restrict__ rots,
                                                    const float* __restrict__ trans,
                                                    const float* __restrict__ intr,
                                                    float* __restrict__ out)
{
    extern __shared__ float smem[];
    float* w2s  = smem + SM_W2S;
    float* c2s  = smem + SM_C2S;
    float* vsh  = smem + SM_VSH;
    float* uni  = smem + SM_UNI;
    float* radE = smem + SM_RADE;
    float* angE = smem + SM_ANGE;
    int*   bins0   = (int*)(smem + SM_BINS);
    int*   headBin = (int*)(smem + SM_HB);
    int*   headS   = (int*)(smem + SM_HS);
    int*   headE   = (int*)(smem + SM_HE);
    float* cam  = smem + SM_CAM;
    float* in4  = smem + SM_IN4;
    int*   scal = (int*)(smem + SM_SCAL);   // [0]=nheads [1]=eqflag

    int blk = blockIdx.x;             // 176 = 2 batches * 88 columns
    int b = blk / FW, wi = blk % FW;
    int t = threadIdx.x;

    // stage precomputed tables (pure copies)
    for (int j = t; j < 3168; j += 512)
        ((float4*)w2s)[j] = ((const float4*)g_w2f)[j];
    if (t < OUT2) c2s[t] = g_c2[t];
    for (int i = t; i <= NR; i += 512) radE[i] = g_radE[i];
    for (int i = t; i <= NT; i += 512) angE[i] = g_angE[i];
    if (t < 9) cam[t] = rots[b*9 + t];
    if (t < 3) cam[9+t] = trans[b*3 + t];
    if (t == 0) {
        in4[0] = intr[b*9 + 0]; in4[1] = intr[b*9 + 4];
        in4[2] = intr[b*9 + 2]; in4[3] = intr[b*9 + 5];
        scal[0] = 0;
        scal[1] = (rots[b*9 + 1] == 0.f && rots[b*9 + 4] == 0.f) ? 1 : 0;
    }

    // load hidden for 32 rows of this column: hsh[pix*HST + c]
    float* hsh = uni;
    {
        int row = t >> 4, c4 = t & 15;
        if (t < 512)
            ((float4*)&hsh[row*HST])[c4] = ((const float4*)&g_h[(b*PIX + row*FW + wi)*HID])[c4];
    }
    __syncthreads();

    // bins for row 0 (overlaps GEMM2 on MUFU/ALU pipes)
    if (t < DEPTH) bins0[t] = computeBin(wi, 0, t, cam, in4, radE, angE);

    // GEMM2: 32 pixels x 198 outputs, f32x2, accumulators-outer (low reg pressure)
    int pix = t & 31, og = t >> 5;     // og 0..15 (one per warp -> broadcast weight LDS)
    {
        u64 acc[13];
#pragma unroll
        for (int k = 0; k < 13; k++) acc[k] = 0;
        bool has13 = (og < 6);
#pragma unroll
        for (int c4 = 0; c4 < 16; c4++) {
            ulonglong2 h2 = *(const ulonglong2*)&hsh[pix*HST + c4*4];
#pragma unroll
            for (int k = 0; k < 12; k++) {
                ulonglong2 wv = *(const ulonglong2*)&w2s[(og + 16*k)*HID + c4*4];
                fma2(acc[k], wv.x, h2.x);
                fma2(acc[k], wv.y, h2.y);
            }
            if (has13) {
                ulonglong2 wv = *(const ulonglong2*)&w2s[(192 + og)*HID + c4*4];
                fma2(acc[12], wv.x, h2.x);
                fma2(acc[12], wv.y, h2.y);
            }
        }
#pragma unroll
        for (int k = 0; k < 12; k++) {
            int o = og + 16*k;
            float2 p = unpack2(acc[k]);
            int s = (o < DEPTH) ? o : o + 2;
            vsh[pix*VST + s] = p.x + p.y + c2s[o];
        }
        if (has13) {
            int o = 192 + og;
            float2 p = unpack2(acc[12]);
            vsh[pix*VST + o + 2] = p.x + p.y + c2s[o];
        }
    }
    __syncthreads();

    // softmax over first 118 channels; 16 warps, 2 pixels each
    int lane = t & 31, warp = t >> 5;
#pragma unroll
    for (int j = 0; j < 2; j++) {
        int p = warp*2 + j;
        float a0 = vsh[p*VST + lane];
        float a1 = vsh[p*VST + lane + 32];
        float a2 = vsh[p*VST + lane + 64];
        float a3 = (lane + 96 < DEPTH) ? vsh[p*VST + lane + 96] : -INFINITY;
        float m = fmaxf(fmaxf(a0,a1), fmaxf(a2,a3));
#pragma unroll
        for (int s = 16; s; s >>= 1) m = fmaxf(m, __shfl_xor_sync(~0u, m, s));
        float e0 = expf(a0 - m), e1 = expf(a1 - m), e2 = expf(a2 - m);
        float e3 = (lane + 96 < DEPTH) ? expf(a3 - m) : 0.f;
        float sm = e0 + e1 + e2 + e3;
#pragma unroll
        for (int s = 16; s; s >>= 1) sm += __shfl_xor_sync(~0u, sm, s);
        float inv = 1.f / sm;
        vsh[p*VST + lane]      = e0*inv;
        vsh[p*VST + lane + 32] = e1*inv;
        vsh[p*VST + lane + 64] = e2*inv;
        if (lane + 96 < DEPTH) vsh[p*VST + lane + 96] = e3*inv;
    }
    __syncthreads();

    float* outb = out + b*C_OUT*NRT;

    if (scal[1]) {
        // run-compress row0 bins (row-independent)
        if (t < DEPTH) {
            int bn = bins0[t];
            if (bn >= 0 && (t == 0 || bins0[t-1] != bn)) {
                int k = t + 1;
                while (k < DEPTH && bins0[k] == bn) k++;
                int s = atomicAdd(&scal[0], 1);
                headBin[s] = bn; headS[s] = t; headE[s] = k;
            }
        }
        __syncthreads();
        int nh = scal[0];
        // per-head, per-row depth weight
        float* wsum = uni;   // hsh dead
        for (int i = t; i < nh*32; i += 512) {
            int h = i >> 5, row = i & 31;
            float s = 0.f;
            for (int d = headS[h]; d < headE[h]; d++) s += vsh[row*VST + d];
            wsum[h*32 + row] = s;
        }
        __syncthreads();
        // aggregate 32 rows; 2 heads per thread; scatter scalar REDs to final layout
        int npair = (nh + 1) >> 1;
        for (int i = t; i < npair*20; i += 512) {
            int hp = i/20, q = i - hp*20;
            int h0 = hp*2, h1 = h0 + 1;
            bool two = (h1 < nh);
            float4 A = make_float4(0.f,0.f,0.f,0.f);
            float4 Bv = make_float4(0.f,0.f,0.f,0.f);
#pragma unroll 4
            for (int row = 0; row < 32; row++) {
                float4 f = *(const float4*)&vsh[row*VST + FOFF + q*4];
                float w0 = wsum[h0*32 + row];
                A.x += w0*f.x; A.y += w0*f.y; A.z += w0*f.z; A.w += w0*f.w;
                if (two) {
                    float w1 = wsum[h1*32 + row];
                    Bv.x += w1*f.x; Bv.y += w1*f.y; Bv.z += w1*f.z; Bv.w += w1*f.w;
                }
            }
            float* p0 = outb + (q*4)*NRT + headBin[h0];
            redadd(p0,          A.x);
            redadd(p0 +   NRT,  A.y);
            redadd(p0 + 2*NRT,  A.z);
            redadd(p0 + 3*NRT,  A.w);
            if (two) {
                float* p1 = outb + (q*4)*NRT + headBin[h1];
                redadd(p1,          Bv.x);
                redadd(p1 +   NRT,  Bv.y);
                redadd(p1 + 2*NRT,  Bv.z);
                redadd(p1 + 3*NRT,  Bv.w);
            }
        }
    } else {
        // generic fallback: per-row scatter
        for (int row = 0; row < 32; row++) {
            __syncthreads();
            if (t == 0) scal[0] = 0;
            __syncthreads();
            if (t < DEPTH) bins0[t] = computeBin(wi, row, t, cam, in4, radE, angE);
            __syncthreads();
            if (t < DEPTH) {
                int bn = bins0[t];
                if (bn >= 0 && (t == 0 || bins0[t-1] != bn)) {
                    int k = t + 1;
                    while (k < DEPTH && bins0[k] == bn) k++;
                    float s = 0.f;
                    for (int d = t; d < k; d++) s += vsh[row*VST + d];
                    int sN = atomicAdd(&scal[0], 1);
                    headBin[sN] = bn;
                    headS[sN] = __float_as_int(s);
                }
            }
            __syncthreads();
            int nh = scal[0];
            for (int i = t; i < nh*20; i += 512) {
                int h = i/20, q = i - h*20;
                float w = __int_as_float(headS[h]);
                const float* f = &vsh[row*VST + FOFF + q*4];
                float* p0 = outb + (q*4)*NRT + headBin[h];
                redadd(p0,          w*f[0]);
                redadd(p0 +   NRT,  w*f[1]);
                redadd(p0 + 2*NRT,  w*f[2]);
                redadd(p0 + 3*NRT,  w*f[3]);
            }
        }
    }
}

// ---------------- launch ----------------
extern "C" void kernel_launch(void* const* d_in, const int* in_sizes, int n_in,
                              void* d_out, int out_size)
{
    const float* x     = (const float*)d_in[0];
    const float* rots  = (const float*)d_in[1];
    const float* trans = (const float*)d_in[2];
    const float* intr  = (const float*)d_in[3];
    const float* w1    = (const float*)d_in[4];
    const float* b1    = (const float*)d_in[5];
    const float* g1    = (const float*)d_in[6];
    const float* be1   = (const float*)d_in[7];
    const float* m1    = (const float*)d_in[8];
    const float* v1    = (const float*)d_in[9];
    const float* w2    = (const float*)d_in[10];
    const float* b2    = (const float*)d_in[11];
    const float* g2    = (const float*)d_in[12];
    const float* be2   = (const float*)d_in[13];
    const float* m2    = (const float*)d_in[14];
    const float* v2    = (const float*)d_in[15];
    float* out = (float*)d_out;

    static int configured = 0;
    if (!configured) {
        cudaFuncSetAttribute(k23_fused, cudaFuncAttributeMaxDynamicSharedMemorySize, K23_SMEM);
        configured = 1;
    }

    k1_gemm1<<<489, 256>>>(x, w1, b1, g1, be1, m1, v1,
                           w2, b2, g2, be2, m2, v2, out);
    k23_fused<<<176, 512, K23_SMEM>>>(rots, trans, intr, out);
}